// round 1
// baseline (speedup 1.0000x reference)
#include <cuda_runtime.h>
#include <math_constants.h>

#define EPSV 1e-5f

// Problem constants
#define NN   2304      // H*W = 48*48
#define NHEAD 8
#define KDIM 32
#define DDIM 128
#define CCH  256
#define DHCH 1024
#define BB   4

// Scratch (device globals -- allocation-free rule)
__device__ float g_q[BB * CCH * NN];
__device__ float g_k[BB * CCH * NN];
__device__ float g_v[BB * DHCH * NN];
__device__ float g_xx[BB * DHCH * NN];

// ---------------------------------------------------------------------------
// GEMM + BN:  Y[b,o,n] = (g[o]/sqrt(1+eps)) * sum_c W[o,c] * act(X[b,c,n]) + beta[o]
// Tiles: BM=64 (o), BN=64 (n), BK=16. 256 threads, 4x4 microtile per thread.
// ---------------------------------------------------------------------------
__global__ void gemm_bn_kernel(const float* __restrict__ X, const float* __restrict__ W,
                               const float* __restrict__ gbn, const float* __restrict__ bbn,
                               float* __restrict__ Y, int C, int O, int relu_in)
{
    __shared__ float sA[16][68];   // [c][o], padded for alignment/banks
    __shared__ float sB[16][64];   // [c][n]

    const int b  = blockIdx.z;
    const int o0 = blockIdx.y * 64;
    const int n0 = blockIdx.x * 64;
    const int tid = threadIdx.x;
    const int tx = tid & 15;       // n microtile
    const int ty = tid >> 4;       // o microtile

    float acc[4][4];
    #pragma unroll
    for (int i = 0; i < 4; i++)
        #pragma unroll
        for (int j = 0; j < 4; j++) acc[i][j] = 0.f;

    const float* Xb = X + (size_t)b * C * NN;

    for (int c0 = 0; c0 < C; c0 += 16) {
        // Load W tile: 64 o x 16 c  -> sA[c][o]
        #pragma unroll
        for (int l = 0; l < 4; l++) {
            int t = tid + l * 256;
            int o = t >> 4, c = t & 15;
            sA[c][o] = W[(size_t)(o0 + o) * C + c0 + c];
        }
        // Load X tile: 16 c x 64 n -> sB[c][n]  (coalesced over n)
        #pragma unroll
        for (int l = 0; l < 4; l++) {
            int t = tid + l * 256;
            int c = t >> 6, n = t & 63;
            float v = Xb[(size_t)(c0 + c) * NN + n0 + n];
            if (relu_in) v = fmaxf(v, 0.f);
            sB[c][n] = v;
        }
        __syncthreads();

        #pragma unroll
        for (int kk = 0; kk < 16; kk++) {
            float4 a4 = *(const float4*)&sA[kk][ty * 4];
            float4 b4 = *(const float4*)&sB[kk][tx * 4];
            acc[0][0] += a4.x * b4.x; acc[0][1] += a4.x * b4.y; acc[0][2] += a4.x * b4.z; acc[0][3] += a4.x * b4.w;
            acc[1][0] += a4.y * b4.x; acc[1][1] += a4.y * b4.y; acc[1][2] += a4.y * b4.z; acc[1][3] += a4.y * b4.w;
            acc[2][0] += a4.z * b4.x; acc[2][1] += a4.z * b4.y; acc[2][2] += a4.z * b4.z; acc[2][3] += a4.z * b4.w;
            acc[3][0] += a4.w * b4.x; acc[3][1] += a4.w * b4.y; acc[3][2] += a4.w * b4.z; acc[3][3] += a4.w * b4.w;
        }
        __syncthreads();
    }

    const float rs = rsqrtf(1.f + EPSV);
    #pragma unroll
    for (int i = 0; i < 4; i++) {
        int o = o0 + ty * 4 + i;
        float s = gbn[o] * rs;
        float be = bbn[o];
        #pragma unroll
        for (int j = 0; j < 4; j++) {
            Y[((size_t)b * O + o) * NN + n0 + tx * 4 + j] = acc[i][j] * s + be;
        }
    }
}

// ---------------------------------------------------------------------------
// Fused attention: per (b, h, 64-query tile), stream keys in tiles of 32 with
// online softmax. Q^T K -> softmax -> * V^T accumulated in registers.
// ---------------------------------------------------------------------------
__global__ void attn_kernel(const float* __restrict__ Q, const float* __restrict__ K,
                            const float* __restrict__ V, float* __restrict__ XX)
{
    __shared__ float sQ[64][36];    // [q][kd] transposed, padded
    __shared__ float sK[32][36];    // [m][kd] transposed, padded
    __shared__ float sV[128][32];   // [d][m]
    __shared__ float sS[64][36];    // [q][m] scores / probs, padded
    __shared__ float sM[64], sL[64], sFac[64];

    const int n0 = blockIdx.x * 64;
    const int h  = blockIdx.y;
    const int b  = blockIdx.z;
    const int tid = threadIdx.x;

    const float* Qb = Q + ((size_t)b * CCH + h * KDIM) * NN;
    const float* Kb = K + ((size_t)b * CCH + h * KDIM) * NN;
    const float* Vb = V + ((size_t)b * DHCH + h * DDIM) * NN;

    // Load Q tile transposed (32 kd x 64 q, coalesced over q)
    #pragma unroll
    for (int l = 0; l < 8; l++) {
        int t = tid + l * 256;
        int kd = t >> 6, q = t & 63;
        sQ[q][kd] = Qb[(size_t)kd * NN + n0 + q];
    }
    if (tid < 64) { sM[tid] = -CUDART_INF_F; sL[tid] = 0.f; }

    float acc[32];
    #pragma unroll
    for (int i = 0; i < 32; i++) acc[i] = 0.f;

    const int q_l = tid & 63;      // accumulate phase: query
    const int dg  = tid >> 6;      // accumulate phase: d-chunk 0..3
    const int d0  = dg * 32;
    const int m_l = tid & 31;      // score phase: key index
    const int qg  = tid >> 5;      // score phase: 8-query group

    __syncthreads();

    for (int m0 = 0; m0 < NN; m0 += 32) {
        // Load K tile transposed (coalesced over m)
        #pragma unroll
        for (int l = 0; l < 4; l++) {
            int t = tid + l * 256;
            int kd = t >> 5, m = t & 31;
            sK[m][kd] = Kb[(size_t)kd * NN + m0 + m];
        }
        // Load V tile [d][m] (coalesced over m)
        #pragma unroll
        for (int l = 0; l < 16; l++) {
            int t = tid + l * 256;
            int d = t >> 5, m = t & 31;
            sV[d][m] = Vb[(size_t)d * NN + m0 + m];
        }
        __syncthreads();

        // Scores: thread owns key m_l, computes 8 queries
        {
            float4 kr[8];
            #pragma unroll
            for (int i = 0; i < 8; i++) kr[i] = *(const float4*)&sK[m_l][i * 4];
            #pragma unroll
            for (int qi = 0; qi < 8; qi++) {
                int q = qg * 8 + qi;
                float s = 0.f;
                #pragma unroll
                for (int i = 0; i < 8; i++) {
                    float4 q4 = *(const float4*)&sQ[q][i * 4];
                    s += q4.x * kr[i].x + q4.y * kr[i].y + q4.z * kr[i].z + q4.w * kr[i].w;
                }
                sS[q][m_l] = s;
            }
        }
        __syncthreads();

        // Online softmax update (one thread per query row)
        if (tid < 64) {
            int q = tid;
            float mx = -CUDART_INF_F;
            #pragma unroll
            for (int m = 0; m < 32; m++) mx = fmaxf(mx, sS[q][m]);
            float mold = sM[q];
            float mnew = fmaxf(mold, mx);
            float fac = __expf(mold - mnew);
            float sum = 0.f;
            #pragma unroll
            for (int m = 0; m < 32; m++) {
                float p = __expf(sS[q][m] - mnew);
                sS[q][m] = p;
                sum += p;
            }
            sM[q] = mnew;
            sL[q] = sL[q] * fac + sum;
            sFac[q] = fac;
        }
        __syncthreads();

        // Accumulate O: acc[d] = acc[d]*fac + sum_m p[m] * V[d][m]
        {
            float f = sFac[q_l];
            #pragma unroll
            for (int i = 0; i < 32; i++) acc[i] *= f;
            #pragma unroll
            for (int mq = 0; mq < 8; mq++) {
                float4 p4 = *(const float4*)&sS[q_l][mq * 4];
                #pragma unroll
                for (int i = 0; i < 32; i++) {
                    float4 v4 = *(const float4*)&sV[d0 + i][mq * 4];
                    acc[i] += p4.x * v4.x + p4.y * v4.y + p4.z * v4.z + p4.w * v4.w;
                }
            }
        }
        __syncthreads();
    }

    const float inv = 1.f / sL[q_l];
    #pragma unroll
    for (int i = 0; i < 32; i++) {
        XX[((size_t)b * DHCH + h * DDIM + d0 + i) * NN + n0 + q_l] = acc[i] * inv;
    }
}

// ---------------------------------------------------------------------------
extern "C" void kernel_launch(void* const* d_in, const int* in_sizes, int n_in,
                              void* d_out, int out_size)
{
    const float* x  = (const float*)d_in[0];
    const float* wq = (const float*)d_in[1];
    const float* gq = (const float*)d_in[2];
    const float* bq = (const float*)d_in[3];
    const float* wk = (const float*)d_in[4];
    const float* gk = (const float*)d_in[5];
    const float* bk = (const float*)d_in[6];
    const float* wv = (const float*)d_in[7];
    const float* gv = (const float*)d_in[8];
    const float* bv = (const float*)d_in[9];
    const float* wp = (const float*)d_in[10];
    const float* gp = (const float*)d_in[11];
    const float* bp = (const float*)d_in[12];
    float* out = (float*)d_out;

    float *q, *k, *v, *xx;
    cudaGetSymbolAddress((void**)&q,  g_q);
    cudaGetSymbolAddress((void**)&k,  g_k);
    cudaGetSymbolAddress((void**)&v,  g_v);
    cudaGetSymbolAddress((void**)&xx, g_xx);

    dim3 blk(256);

    // Q/K/V projections (+BN)
    gemm_bn_kernel<<<dim3(NN / 64, CCH / 64,  BB), blk>>>(x, wq, gq, bq, q,  CCH, CCH,  0);
    gemm_bn_kernel<<<dim3(NN / 64, CCH / 64,  BB), blk>>>(x, wk, gk, bk, k,  CCH, CCH,  0);
    gemm_bn_kernel<<<dim3(NN / 64, DHCH / 64, BB), blk>>>(x, wv, gv, bv, v,  CCH, DHCH, 0);

    // Fused attention
    attn_kernel<<<dim3(NN / 64, NHEAD, BB), blk>>>(q, k, v, xx);

    // Output projection on relu(xx) (+BN)
    gemm_bn_kernel<<<dim3(NN / 64, CCH / 64, BB), blk>>>(xx, wp, gp, bp, out, DHCH, CCH, 1);
}

// round 3
// speedup vs baseline: 2.4001x; 2.4001x over previous
#include <cuda_runtime.h>
#include <math_constants.h>
#include <cstdint>

#define EPSV 1e-5f

// Problem constants
#define NN    2304
#define NHEAD 8
#define KDIM  32
#define DDIM  128
#define CCH   256
#define DHCH  1024
#define BB    4

// Scratch
__device__ float g_q[BB * CCH * NN];
__device__ float g_k[BB * CCH * NN];
__device__ float g_v[BB * DHCH * NN];
__device__ float g_xx[BB * DHCH * NN];

// ---------------------------------------------------------------------------
// helpers
// ---------------------------------------------------------------------------
__device__ __forceinline__ uint32_t f2tf32(float x) {
    uint32_t r;
    asm("cvt.rna.tf32.f32 %0, %1;" : "=r"(r) : "f"(x));
    return r;
}

__device__ __forceinline__ void mma_tf32(float c[4], uint32_t a0, uint32_t a1,
                                         uint32_t a2, uint32_t a3,
                                         uint32_t b0, uint32_t b1) {
    asm volatile(
        "mma.sync.aligned.m16n8k8.row.col.f32.tf32.tf32.f32 "
        "{%0,%1,%2,%3}, {%4,%5,%6,%7}, {%8,%9}, {%0,%1,%2,%3};\n"
        : "+f"(c[0]), "+f"(c[1]), "+f"(c[2]), "+f"(c[3])
        : "r"(a0), "r"(a1), "r"(a2), "r"(a3), "r"(b0), "r"(b1));
}

// exp on the FMA pipe (no MUFU). |rel err| ~2e-6 for |x| < 30.
__device__ __forceinline__ float fast_exp(float x) {
    float t = x * 1.4426950408889634f;
    float r = rintf(t);
    float f = t - r;
    float p = 0.0013333558f;
    p = fmaf(p, f, 0.0096181291f);
    p = fmaf(p, f, 0.0555041086f);
    p = fmaf(p, f, 0.2402265069f);
    p = fmaf(p, f, 0.6931471806f);
    p = fmaf(p, f, 1.0f);
    int e = (__float2int_rn(r) + 127) << 23;
    return p * __int_as_float(e);
}

// ---------------------------------------------------------------------------
// GEMM + BN (SIMT fp32) -- unchanged from the passing R1 kernel
// ---------------------------------------------------------------------------
__global__ void gemm_bn_kernel(const float* __restrict__ X, const float* __restrict__ W,
                               const float* __restrict__ gbn, const float* __restrict__ bbn,
                               float* __restrict__ Y, int C, int O, int relu_in)
{
    __shared__ float sA[16][68];
    __shared__ float sB[16][64];

    const int b  = blockIdx.z;
    const int o0 = blockIdx.y * 64;
    const int n0 = blockIdx.x * 64;
    const int tid = threadIdx.x;
    const int tx = tid & 15;
    const int ty = tid >> 4;

    float acc[4][4];
    #pragma unroll
    for (int i = 0; i < 4; i++)
        #pragma unroll
        for (int j = 0; j < 4; j++) acc[i][j] = 0.f;

    const float* Xb = X + (size_t)b * C * NN;

    for (int c0 = 0; c0 < C; c0 += 16) {
        #pragma unroll
        for (int l = 0; l < 4; l++) {
            int t = tid + l * 256;
            int o = t >> 4, c = t & 15;
            sA[c][o] = W[(size_t)(o0 + o) * C + c0 + c];
        }
        #pragma unroll
        for (int l = 0; l < 4; l++) {
            int t = tid + l * 256;
            int c = t >> 6, n = t & 63;
            float v = Xb[(size_t)(c0 + c) * NN + n0 + n];
            if (relu_in) v = fmaxf(v, 0.f);
            sB[c][n] = v;
        }
        __syncthreads();

        #pragma unroll
        for (int kk = 0; kk < 16; kk++) {
            float4 a4 = *(const float4*)&sA[kk][ty * 4];
            float4 b4 = *(const float4*)&sB[kk][tx * 4];
            acc[0][0] += a4.x * b4.x; acc[0][1] += a4.x * b4.y; acc[0][2] += a4.x * b4.z; acc[0][3] += a4.x * b4.w;
            acc[1][0] += a4.y * b4.x; acc[1][1] += a4.y * b4.y; acc[1][2] += a4.y * b4.z; acc[1][3] += a4.y * b4.w;
            acc[2][0] += a4.z * b4.x; acc[2][1] += a4.z * b4.y; acc[2][2] += a4.z * b4.z; acc[2][3] += a4.z * b4.w;
            acc[3][0] += a4.w * b4.x; acc[3][1] += a4.w * b4.y; acc[3][2] += a4.w * b4.z; acc[3][3] += a4.w * b4.w;
        }
        __syncthreads();
    }

    const float rs = rsqrtf(1.f + EPSV);
    #pragma unroll
    for (int i = 0; i < 4; i++) {
        int o = o0 + ty * 4 + i;
        float s = gbn[o] * rs;
        float be = bbn[o];
        #pragma unroll
        for (int j = 0; j < 4; j++) {
            Y[((size_t)b * O + o) * NN + n0 + tx * 4 + j] = acc[i][j] * s + be;
        }
    }
}

// ---------------------------------------------------------------------------
// Tensor-core fused attention, tf32 mma.sync. STATIC smem <= 48KB.
//   TQ=64 queries/block, TM=32 keys/tile, 256 threads (8 warps).
//   QK^T : 3xTF32 split (K split in regs).  softmax: no-max, poly exp, register
//   row-sums across all tiles.  P*V: 1xTF32, output as V*P^T -> [d][q].
//   Q smem region is reused by K/V/P after A-fragments are hoisted to regs.
// ---------------------------------------------------------------------------
// pool layout (floats):
//   main loop:  sK  [32][36] @0      (1152)
//               sV  [128][36]@1152   (4608)
//               sP  [64][36] @5760   (2304)
//               sSum[64]     @8064
//   prologue :  sQh [64][36] @0, sQl [64][36] @2304   (overlaps sK/sV)
#define POOL_FLOATS 8128

__global__ __launch_bounds__(256, 2)
void attn_mma_kernel(const float* __restrict__ Q, const float* __restrict__ K,
                     const float* __restrict__ V, float* __restrict__ XX)
{
    __shared__ float pool[POOL_FLOATS];
    float* sK   = pool;           // [32][36]
    float* sV   = pool + 1152;    // [128][36]
    float* sP   = pool + 5760;    // [64][36]
    float* sSum = pool + 8064;    // [64]
    float* sQh  = pool;           // prologue only
    float* sQl  = pool + 2304;    // prologue only

    const int tid  = threadIdx.x;
    const int lane = tid & 31;
    const int w    = tid >> 5;
    const int lg   = lane >> 2;
    const int lt   = lane & 3;

    const int n0 = blockIdx.x * 64;
    const int h  = blockIdx.y;
    const int b  = blockIdx.z;

    const float* Qb = Q + ((size_t)b * CCH + h * KDIM) * NN;
    const float* Kb = K + ((size_t)b * CCH + h * KDIM) * NN;
    const float* Vb = V + ((size_t)b * DHCH + h * DDIM) * NN;

    // ---- prologue: Q tile (64q x 32kd), split hi/lo, [q][kd] stride 36
    #pragma unroll
    for (int i = 0; i < 8; i++) {
        int t = tid + i * 256;
        int kd = t >> 6, q = t & 63;
        float v = Qb[(size_t)kd * NN + n0 + q];
        uint32_t hb = f2tf32(v);
        float hf = __uint_as_float(hb);
        sQh[q * 36 + kd] = hf;
        sQl[q * 36 + kd] = v - hf;
    }
    if (tid < 64) sSum[tid] = 0.f;
    __syncthreads();

    // ---- hoist Q A-fragments; after this Q smem is dead
    const int qrS = (w & 3) * 16 + lg;   // S-phase fragment row (query)
    uint32_t ah[4][4], al[4][4];
    #pragma unroll
    for (int kt = 0; kt < 4; kt++) {
        int c0 = kt * 8 + lt;
        ah[kt][0] = __float_as_uint(sQh[qrS * 36 + c0]);
        ah[kt][1] = __float_as_uint(sQh[(qrS + 8) * 36 + c0]);
        ah[kt][2] = __float_as_uint(sQh[qrS * 36 + c0 + 4]);
        ah[kt][3] = __float_as_uint(sQh[(qrS + 8) * 36 + c0 + 4]);
        al[kt][0] = __float_as_uint(sQl[qrS * 36 + c0]);
        al[kt][1] = __float_as_uint(sQl[(qrS + 8) * 36 + c0]);
        al[kt][2] = __float_as_uint(sQl[qrS * 36 + c0 + 4]);
        al[kt][3] = __float_as_uint(sQl[(qrS + 8) * 36 + c0 + 4]);
    }

    float Oc[8][4];
    #pragma unroll
    for (int nt = 0; nt < 8; nt++)
        #pragma unroll
        for (int j = 0; j < 4; j++) Oc[nt][j] = 0.f;

    float rsum0 = 0.f, rsum1 = 0.f;      // register row sums across all tiles
    const int n0w = (w >> 2) * 16;       // S-phase column base (0 or 16)
    const int d0w = w * 16;              // PV-phase d base

    for (int m0 = 0; m0 < NN; m0 += 32) {
        __syncthreads();   // Q hoist done (iter 0) / previous PV done

        // load K tile (32kd x 32m) -> sK[m][kd], fp32 (coalesced over m)
        #pragma unroll
        for (int l = 0; l < 4; l++) {
            int t = tid + l * 256;
            int kd = t >> 5, m = t & 31;
            sK[m * 36 + kd] = Kb[(size_t)kd * NN + m0 + m];
        }
        // load V tile (128d x 32m) -> sV[d][m], float4
        #pragma unroll
        for (int l = 0; l < 4; l++) {
            int t = tid + l * 256;
            int d = t >> 3, mq = t & 7;
            float4 vv = *(const float4*)&Vb[(size_t)d * NN + m0 + mq * 4];
            *(float4*)&sV[d * 36 + mq * 4] = vv;
        }
        __syncthreads();

        // ---- S = Q K^T (3xTF32); warp covers 16 q x 16 m
        float sc[2][4];
        #pragma unroll
        for (int nt = 0; nt < 2; nt++) {
            sc[nt][0] = sc[nt][1] = sc[nt][2] = sc[nt][3] = 0.f;
            int mrow = (n0w + nt * 8 + lg) * 36;
            #pragma unroll
            for (int kt = 0; kt < 4; kt++) {
                int kc = kt * 8 + lt;
                float kv0 = sK[mrow + kc];
                float kv1 = sK[mrow + kc + 4];
                uint32_t bh0 = f2tf32(kv0);
                uint32_t bh1 = f2tf32(kv1);
                uint32_t bl0 = __float_as_uint(kv0 - __uint_as_float(bh0));
                uint32_t bl1 = __float_as_uint(kv1 - __uint_as_float(bh1));
                mma_tf32(sc[nt], ah[kt][0], ah[kt][1], ah[kt][2], ah[kt][3], bh0, bh1);
                mma_tf32(sc[nt], ah[kt][0], ah[kt][1], ah[kt][2], ah[kt][3], bl0, bl1);
                mma_tf32(sc[nt], al[kt][0], al[kt][1], al[kt][2], al[kt][3], bh0, bh1);
            }
        }

        // ---- P = exp(S), accumulate register row-sums, stage to sP[q][m]
        #pragma unroll
        for (int nt = 0; nt < 2; nt++) {
            float p0 = fast_exp(sc[nt][0]);
            float p1 = fast_exp(sc[nt][1]);
            float p2 = fast_exp(sc[nt][2]);
            float p3 = fast_exp(sc[nt][3]);
            rsum0 += p0 + p1;
            rsum1 += p2 + p3;
            int col = n0w + nt * 8 + 2 * lt;
            *(float2*)&sP[qrS * 36 + col]       = make_float2(p0, p1);
            *(float2*)&sP[(qrS + 8) * 36 + col] = make_float2(p2, p3);
        }
        __syncthreads();

        // ---- O += V * P^T (1xTF32); warp: 16 d-rows x 64 q-cols
        #pragma unroll
        for (int kt = 0; kt < 4; kt++) {
            int kc = kt * 8 + lt;
            uint32_t va0 = __float_as_uint(sV[(d0w + lg) * 36 + kc]);
            uint32_t va1 = __float_as_uint(sV[(d0w + 8 + lg) * 36 + kc]);
            uint32_t va2 = __float_as_uint(sV[(d0w + lg) * 36 + kc + 4]);
            uint32_t va3 = __float_as_uint(sV[(d0w + 8 + lg) * 36 + kc + 4]);
            #pragma unroll
            for (int nt = 0; nt < 8; nt++) {
                uint32_t pb0 = __float_as_uint(sP[(nt * 8 + lg) * 36 + kc]);
                uint32_t pb1 = __float_as_uint(sP[(nt * 8 + lg) * 36 + kc + 4]);
                mma_tf32(Oc[nt], va0, va1, va2, va3, pb0, pb1);
            }
        }
    }

    // ---- fold row sums (each (row, col-half) pair lives in 2 warps)
    rsum0 += __shfl_xor_sync(0xffffffffu, rsum0, 1);
    rsum0 += __shfl_xor_sync(0xffffffffu, rsum0, 2);
    rsum1 += __shfl_xor_sync(0xffffffffu, rsum1, 1);
    rsum1 += __shfl_xor_sync(0xffffffffu, rsum1, 2);
    __syncthreads();   // last PV done before touching sSum zone semantics
    if (lt == 0) {
        atomicAdd(&sSum[qrS], rsum0);
        atomicAdd(&sSum[qrS + 8], rsum1);
    }
    __syncthreads();
    if (tid < 64) sSum[tid] = 1.0f / sSum[tid];
    __syncthreads();

    // ---- normalize + store [d][q], coalesced float2
    float* XXb = XX + ((size_t)b * DHCH + h * DDIM) * NN;
    #pragma unroll
    for (int nt = 0; nt < 8; nt++) {
        int qc = nt * 8 + 2 * lt;
        float i0 = sSum[qc], i1 = sSum[qc + 1];
        float2 o0 = make_float2(Oc[nt][0] * i0, Oc[nt][1] * i1);
        float2 o1 = make_float2(Oc[nt][2] * i0, Oc[nt][3] * i1);
        *(float2*)&XXb[(size_t)(d0w + lg) * NN + n0 + qc] = o0;
        *(float2*)&XXb[(size_t)(d0w + 8 + lg) * NN + n0 + qc] = o1;
    }
}

// ---------------------------------------------------------------------------
extern "C" void kernel_launch(void* const* d_in, const int* in_sizes, int n_in,
                              void* d_out, int out_size)
{
    const float* x  = (const float*)d_in[0];
    const float* wq = (const float*)d_in[1];
    const float* gq = (const float*)d_in[2];
    const float* bq = (const float*)d_in[3];
    const float* wk = (const float*)d_in[4];
    const float* gk = (const float*)d_in[5];
    const float* bk = (const float*)d_in[6];
    const float* wv = (const float*)d_in[7];
    const float* gv = (const float*)d_in[8];
    const float* bv = (const float*)d_in[9];
    const float* wp = (const float*)d_in[10];
    const float* gp = (const float*)d_in[11];
    const float* bp = (const float*)d_in[12];
    float* out = (float*)d_out;

    float *q, *k, *v, *xx;
    cudaGetSymbolAddress((void**)&q,  g_q);
    cudaGetSymbolAddress((void**)&k,  g_k);
    cudaGetSymbolAddress((void**)&v,  g_v);
    cudaGetSymbolAddress((void**)&xx, g_xx);

    dim3 blk(256);

    gemm_bn_kernel<<<dim3(NN / 64, CCH / 64,  BB), blk>>>(x, wq, gq, bq, q,  CCH, CCH,  0);
    gemm_bn_kernel<<<dim3(NN / 64, CCH / 64,  BB), blk>>>(x, wk, gk, bk, k,  CCH, CCH,  0);
    gemm_bn_kernel<<<dim3(NN / 64, DHCH / 64, BB), blk>>>(x, wv, gv, bv, v,  CCH, DHCH, 0);

    attn_mma_kernel<<<dim3(NN / 64, NHEAD, BB), blk>>>(q, k, v, xx);

    gemm_bn_kernel<<<dim3(NN / 64, CCH / 64, BB), blk>>>(xx, wp, gp, bp, out, DHCH, CCH, 1);
}

// round 5
// speedup vs baseline: 3.0371x; 1.2654x over previous
#include <cuda_runtime.h>
#include <math_constants.h>
#include <cstdint>

#define EPSV 1e-5f

// Problem constants
#define NN    2304
#define NHEAD 8
#define KDIM  32
#define DDIM  128
#define CCH   256
#define DHCH  1024
#define BB    4

// Scratch (allocation-free rule: device globals)
__device__ float g_xr[BB * CCH * NN];     // x rounded to tf32
__device__ float g_qh[BB * CCH * NN];
__device__ float g_ql[BB * CCH * NN];
__device__ float g_kh[BB * CCH * NN];
__device__ float g_kl[BB * CCH * NN];
__device__ float g_v [BB * DHCH * NN];    // tf32-rounded V
__device__ float g_xx[BB * DHCH * NN];    // relu(rna(attn out)) -- tf32 values
__device__ float g_wqh[CCH * CCH],  g_wql[CCH * CCH];
__device__ float g_wkh[CCH * CCH],  g_wkl[CCH * CCH];
__device__ float g_wvh[DHCH * CCH], g_wvl[DHCH * CCH];
__device__ float g_wph[CCH * DHCH], g_wpl[CCH * DHCH];

// ---------------------------------------------------------------------------
// helpers
// ---------------------------------------------------------------------------
__device__ __forceinline__ uint32_t f2tf32(float x) {
    uint32_t r;
    asm("cvt.rna.tf32.f32 %0, %1;" : "=r"(r) : "f"(x));
    return r;
}
__device__ __forceinline__ float rn_tf32(float x) {
    return __uint_as_float(f2tf32(x));
}

__device__ __forceinline__ void mma_tf32(float c[4], uint32_t a0, uint32_t a1,
                                         uint32_t a2, uint32_t a3,
                                         uint32_t b0, uint32_t b1) {
    asm volatile(
        "mma.sync.aligned.m16n8k8.row.col.f32.tf32.tf32.f32 "
        "{%0,%1,%2,%3}, {%4,%5,%6,%7}, {%8,%9}, {%0,%1,%2,%3};\n"
        : "+f"(c[0]), "+f"(c[1]), "+f"(c[2]), "+f"(c[3])
        : "r"(a0), "r"(a1), "r"(a2), "r"(a3), "r"(b0), "r"(b1));
}

__device__ __forceinline__ void cp16(void* sdst, const void* gsrc) {
    uint32_t s = (uint32_t)__cvta_generic_to_shared(sdst);
    asm volatile("cp.async.ca.shared.global [%0], [%1], 16;" :: "r"(s), "l"(gsrc));
}
__device__ __forceinline__ void cp_commit() {
    asm volatile("cp.async.commit_group;");
}
template <int N>
__device__ __forceinline__ void cp_wait() {
    asm volatile("cp.async.wait_group %0;" :: "n"(N));
}

// exp on the FMA pipe (no MUFU). |rel err| ~2e-6 for |x| < 30.
__device__ __forceinline__ float fast_exp(float x) {
    float t = x * 1.4426950408889634f;
    float r = rintf(t);
    float f = t - r;
    float p = 0.0013333558f;
    p = fmaf(p, f, 0.0096181291f);
    p = fmaf(p, f, 0.0555041086f);
    p = fmaf(p, f, 0.2402265069f);
    p = fmaf(p, f, 0.6931471806f);
    p = fmaf(p, f, 1.0f);
    int e = (__float2int_rn(r) + 127) << 23;
    return p * __int_as_float(e);
}

// ---------------------------------------------------------------------------
// Prep kernels
// ---------------------------------------------------------------------------
__global__ void round_tf32_kernel(const float* __restrict__ src, float* __restrict__ dst, int n) {
    for (int i = blockIdx.x * blockDim.x + threadIdx.x; i < n; i += gridDim.x * blockDim.x)
        dst[i] = rn_tf32(src[i]);
}
__global__ void split_tf32_kernel(const float* __restrict__ src, float* __restrict__ h,
                                  float* __restrict__ l, int n) {
    for (int i = blockIdx.x * blockDim.x + threadIdx.x; i < n; i += gridDim.x * blockDim.x) {
        float v = src[i];
        float hv = rn_tf32(v);
        h[i] = hv;
        l[i] = v - hv;
    }
}

// ---------------------------------------------------------------------------
// tf32 MMA projection + BN.
//   Y[b,o,n] = (g[o]/sqrt(1+eps)) * sum_c (Wh+Wl)[o,c] * Xr[b,c,n] + beta[o]
// Xr values are already tf32. Tiles 64o x 64n, k-steps of 16, cp.async double
// buffered. 256 threads, 8 warps: warp = 16o x 32n.
// mode 0: plain store to Y0.  mode 1: split store (Y0=hi, Y1=lo).
// mode 2: tf32-rounded store to Y0.
// ---------------------------------------------------------------------------
#define WSTR 20
#define XSTR 68     // X tile row width 64 + 4 pad (272B rows, 16B-aligned)
__global__ __launch_bounds__(256, 3)
void proj_mma_kernel(const float* __restrict__ Xr,
                     const float* __restrict__ Wh, const float* __restrict__ Wl,
                     const float* __restrict__ gbn, const float* __restrict__ bbn,
                     float* __restrict__ Y0, float* __restrict__ Y1,
                     int C, int O, int mode)
{
    __shared__ __align__(16) float sWh[2][64 * WSTR];
    __shared__ __align__(16) float sWl[2][64 * WSTR];
    __shared__ __align__(16) float sX [2][16 * XSTR];

    const int b  = blockIdx.z;
    const int o0 = blockIdx.y * 64;
    const int n0 = blockIdx.x * 64;
    const int tid = threadIdx.x;
    const int lane = tid & 31;
    const int w  = tid >> 5;
    const int lg = lane >> 2;
    const int lt = lane & 3;
    const int ow = (w & 3) * 16;
    const int nw = (w >> 2) * 32;

    const float* Xb = Xr + (size_t)b * C * NN;

    // loader: W tile 64o x 16c, X tile 16c x 64n
    const int wlo = tid >> 2, wlc = (tid & 3) * 4;
    const int xlc = tid >> 4, xln = (tid & 15) * 4;

    const int steps = C / 16;

    // prologue load step 0
    {
        cp16(&sWh[0][wlo * WSTR + wlc], Wh + (size_t)(o0 + wlo) * C + wlc);
        cp16(&sWl[0][wlo * WSTR + wlc], Wl + (size_t)(o0 + wlo) * C + wlc);
        cp16(&sX [0][xlc * XSTR + xln], Xb + (size_t)xlc * NN + n0 + xln);
    }
    cp_commit();

    float Oc[4][4];
    #pragma unroll
    for (int nt = 0; nt < 4; nt++)
        #pragma unroll
        for (int j = 0; j < 4; j++) Oc[nt][j] = 0.f;

    for (int s = 0; s < steps; s++) {
        const int cur = s & 1, nxt = cur ^ 1;
        if (s + 1 < steps) {
            int c0 = (s + 1) * 16;
            cp16(&sWh[nxt][wlo * WSTR + wlc], Wh + (size_t)(o0 + wlo) * C + c0 + wlc);
            cp16(&sWl[nxt][wlo * WSTR + wlc], Wl + (size_t)(o0 + wlo) * C + c0 + wlc);
            cp16(&sX [nxt][xlc * XSTR + xln], Xb + (size_t)(c0 + xlc) * NN + n0 + xln);
        }
        cp_commit();
        cp_wait<1>();
        __syncthreads();

        #pragma unroll
        for (int kk = 0; kk < 2; kk++) {
            int kc = kk * 8 + lt;
            uint32_t ah0 = __float_as_uint(sWh[cur][(ow + lg) * WSTR + kc]);
            uint32_t ah1 = __float_as_uint(sWh[cur][(ow + 8 + lg) * WSTR + kc]);
            uint32_t ah2 = __float_as_uint(sWh[cur][(ow + lg) * WSTR + kc + 4]);
            uint32_t ah3 = __float_as_uint(sWh[cur][(ow + 8 + lg) * WSTR + kc + 4]);
            uint32_t al0 = __float_as_uint(sWl[cur][(ow + lg) * WSTR + kc]);
            uint32_t al1 = __float_as_uint(sWl[cur][(ow + 8 + lg) * WSTR + kc]);
            uint32_t al2 = __float_as_uint(sWl[cur][(ow + lg) * WSTR + kc + 4]);
            uint32_t al3 = __float_as_uint(sWl[cur][(ow + 8 + lg) * WSTR + kc + 4]);
            #pragma unroll
            for (int nt = 0; nt < 4; nt++) {
                int nc = nw + nt * 8 + lg;
                uint32_t b0 = __float_as_uint(sX[cur][kc * XSTR + nc]);
                uint32_t b1 = __float_as_uint(sX[cur][(kc + 4) * XSTR + nc]);
                mma_tf32(Oc[nt], ah0, ah1, ah2, ah3, b0, b1);
                mma_tf32(Oc[nt], al0, al1, al2, al3, b0, b1);
            }
        }
        __syncthreads();
    }

    // epilogue: BN + store per mode
    const float rs = rsqrtf(1.f + EPSV);
    const int oa = o0 + ow + lg;
    const int ob = oa + 8;
    const float sa = gbn[oa] * rs, ba = bbn[oa];
    const float sb = gbn[ob] * rs, bb2 = bbn[ob];

    #pragma unroll
    for (int nt = 0; nt < 4; nt++) {
        int n = n0 + nw + nt * 8 + 2 * lt;
        float ya0 = Oc[nt][0] * sa + ba;
        float ya1 = Oc[nt][1] * sa + ba;
        float yb0 = Oc[nt][2] * sb + bb2;
        float yb1 = Oc[nt][3] * sb + bb2;
        size_t ia = ((size_t)b * O + oa) * NN + n;
        size_t ib = ((size_t)b * O + ob) * NN + n;
        if (mode == 0) {
            *(float2*)&Y0[ia] = make_float2(ya0, ya1);
            *(float2*)&Y0[ib] = make_float2(yb0, yb1);
        } else if (mode == 1) {
            float ha0 = rn_tf32(ya0), ha1 = rn_tf32(ya1);
            float hb0 = rn_tf32(yb0), hb1 = rn_tf32(yb1);
            *(float2*)&Y0[ia] = make_float2(ha0, ha1);
            *(float2*)&Y0[ib] = make_float2(hb0, hb1);
            *(float2*)&Y1[ia] = make_float2(ya0 - ha0, ya1 - ha1);
            *(float2*)&Y1[ib] = make_float2(yb0 - hb0, yb1 - hb1);
        } else {
            *(float2*)&Y0[ia] = make_float2(rn_tf32(ya0), rn_tf32(ya1));
            *(float2*)&Y0[ib] = make_float2(rn_tf32(yb0), rn_tf32(yb1));
        }
    }
}

// ---------------------------------------------------------------------------
// Tensor-core fused attention. Q/K pre-split (hi/lo), V pre-rounded.
//   TQ=64 q/block, TM=32 keys/tile, 256 threads.
//   K [kd][m] stride 40, cp.async double-buffered.
//   V [d][m] stride 36, cp.async, load overlaps S phase.
//   P rna-rounded before row-sum AND mma (consistent normalization).
//   Epilogue stores relu(rna(o)) -> final projection is a pure GEMM.
// pool (floats): kh0@0 kl0@1280 kh1@2560 kl1@3840 (each 32*40)
//                V@5120 (128*36=4608)  P@9728 (64*36=2304)  sums@12032 (64)
// prologue staging: Qh@5120 (2304), Ql@9728 (2304)
// ---------------------------------------------------------------------------
#define KSTR 40
#define VSTR 36
#define PSTR 36
#define POOL_FLOATS 12096

__global__ __launch_bounds__(256, 2)
void attn_mma_kernel(const float* __restrict__ Qh, const float* __restrict__ Ql,
                     const float* __restrict__ Kh, const float* __restrict__ Kl,
                     const float* __restrict__ V, float* __restrict__ XX)
{
    __shared__ __align__(16) float pool[POOL_FLOATS];
    float* sKh0 = pool;
    float* sKl0 = pool + 1280;
    float* sKh1 = pool + 2560;
    float* sKl1 = pool + 3840;
    float* sV   = pool + 5120;
    float* sP   = pool + 9728;
    float* sSum = pool + 12032;
    float* stQh = pool + 5120;   // prologue staging
    float* stQl = pool + 9728;

    const int tid  = threadIdx.x;
    const int lane = tid & 31;
    const int w    = tid >> 5;
    const int lg   = lane >> 2;
    const int lt   = lane & 3;

    const int n0 = blockIdx.x * 64;
    const int h  = blockIdx.y;
    const int b  = blockIdx.z;

    const float* QhB = Qh + ((size_t)b * CCH + h * KDIM) * NN;
    const float* QlB = Ql + ((size_t)b * CCH + h * KDIM) * NN;
    const float* KhB = Kh + ((size_t)b * CCH + h * KDIM) * NN;
    const float* KlB = Kl + ((size_t)b * CCH + h * KDIM) * NN;
    const float* VB  = V  + ((size_t)b * DHCH + h * DDIM) * NN;

    // cp.async thread mapping for K (32kd x 32m) and V (128d x 32m)
    const int kkd = tid >> 3;            // 0..31
    const int kch = (tid & 7) * 4;       // m offset
    const int vd0 = tid >> 3;            // + j*32
    const int vch = (tid & 7) * 4;

    // ---- issue K tile 0
    cp16(sKh0 + kkd * KSTR + kch, KhB + (size_t)kkd * NN + kch);
    cp16(sKl0 + kkd * KSTR + kch, KlB + (size_t)kkd * NN + kch);
    cp_commit();                         // group: K0

    // ---- stage Q (coalesced over q), init sums
    #pragma unroll
    for (int i = 0; i < 8; i++) {
        int t = tid + i * 256;
        int kd = t >> 6, q = t & 63;
        stQh[q * 36 + kd] = QhB[(size_t)kd * NN + n0 + q];
        stQl[q * 36 + kd] = QlB[(size_t)kd * NN + n0 + q];
    }
    if (tid < 64) sSum[tid] = 0.f;
    __syncthreads();

    // ---- hoist Q A-fragments
    const int qrS = (w & 3) * 16 + lg;
    uint32_t ah[4][4], al[4][4];
    #pragma unroll
    for (int kt = 0; kt < 4; kt++) {
        int c0 = kt * 8 + lt;
        ah[kt][0] = __float_as_uint(stQh[qrS * 36 + c0]);
        ah[kt][1] = __float_as_uint(stQh[(qrS + 8) * 36 + c0]);
        ah[kt][2] = __float_as_uint(stQh[qrS * 36 + c0 + 4]);
        ah[kt][3] = __float_as_uint(stQh[(qrS + 8) * 36 + c0 + 4]);
        al[kt][0] = __float_as_uint(stQl[qrS * 36 + c0]);
        al[kt][1] = __float_as_uint(stQl[(qrS + 8) * 36 + c0]);
        al[kt][2] = __float_as_uint(stQl[qrS * 36 + c0 + 4]);
        al[kt][3] = __float_as_uint(stQl[(qrS + 8) * 36 + c0 + 4]);
    }
    __syncthreads();   // Q staging regions now free

    // ---- issue V tile 0
    #pragma unroll
    for (int j = 0; j < 4; j++) {
        int d = vd0 + j * 32;
        cp16(sV + d * VSTR + vch, VB + (size_t)d * NN + vch);
    }
    cp_commit();                         // groups: {K0, V0}

    float Oc[8][4];
    #pragma unroll
    for (int nt = 0; nt < 8; nt++)
        #pragma unroll
        for (int j = 0; j < 4; j++) Oc[nt][j] = 0.f;

    float rsum0 = 0.f, rsum1 = 0.f;
    const int n0w = (w >> 2) * 16;
    const int d0w = w * 16;

    const int NTILE = NN / 32;           // 72
    for (int i = 0; i < NTILE; i++) {
        const int m0 = i * 32;
        float* curKh = (i & 1) ? sKh1 : sKh0;
        float* curKl = (i & 1) ? sKl1 : sKl0;
        float* nxtKh = (i & 1) ? sKh0 : sKh1;
        float* nxtKl = (i & 1) ? sKl0 : sKl1;

        // issue K(i+1)
        if (i + 1 < NTILE) {
            int m1 = m0 + 32;
            cp16(nxtKh + kkd * KSTR + kch, KhB + (size_t)kkd * NN + m1 + kch);
            cp16(nxtKl + kkd * KSTR + kch, KlB + (size_t)kkd * NN + m1 + kch);
        }
        cp_commit();                     // {K_i, V_i, K_{i+1}}
        cp_wait<2>();                    // K_i done
        __syncthreads();

        // ---- S = Q K^T (3xTF32); warp: 16 q x 16 m
        float sc[2][4];
        #pragma unroll
        for (int nt = 0; nt < 2; nt++) {
            sc[nt][0] = sc[nt][1] = sc[nt][2] = sc[nt][3] = 0.f;
            int mc = n0w + nt * 8 + lg;
            #pragma unroll
            for (int kt = 0; kt < 4; kt++) {
                int kc = kt * 8 + lt;
                uint32_t bh0 = __float_as_uint(curKh[kc * KSTR + mc]);
                uint32_t bh1 = __float_as_uint(curKh[(kc + 4) * KSTR + mc]);
                uint32_t bl0 = __float_as_uint(curKl[kc * KSTR + mc]);
                uint32_t bl1 = __float_as_uint(curKl[(kc + 4) * KSTR + mc]);
                mma_tf32(sc[nt], ah[kt][0], ah[kt][1], ah[kt][2], ah[kt][3], bh0, bh1);
                mma_tf32(sc[nt], ah[kt][0], ah[kt][1], ah[kt][2], ah[kt][3], bl0, bl1);
                mma_tf32(sc[nt], al[kt][0], al[kt][1], al[kt][2], al[kt][3], bh0, bh1);
            }
        }

        cp_wait<1>();                    // V_i done (K_{i+1} still in flight)

        // ---- P = rna(exp(S)); row sums from the ROUNDED values (consistent)
        #pragma unroll
        for (int nt = 0; nt < 2; nt++) {
            float p0 = rn_tf32(fast_exp(sc[nt][0]));
            float p1 = rn_tf32(fast_exp(sc[nt][1]));
            float p2 = rn_tf32(fast_exp(sc[nt][2]));
            float p3 = rn_tf32(fast_exp(sc[nt][3]));
            rsum0 += p0 + p1;
            rsum1 += p2 + p3;
            int col = n0w + nt * 8 + 2 * lt;
            *(float2*)&sP[qrS * PSTR + col]       = make_float2(p0, p1);
            *(float2*)&sP[(qrS + 8) * PSTR + col] = make_float2(p2, p3);
        }
        __syncthreads();                 // V + P visible to all

        // ---- O += V * P^T; warp: 16 d x 64 q
        #pragma unroll
        for (int kt = 0; kt < 4; kt++) {
            int kc = kt * 8 + lt;
            uint32_t va0 = __float_as_uint(sV[(d0w + lg) * VSTR + kc]);
            uint32_t va1 = __float_as_uint(sV[(d0w + 8 + lg) * VSTR + kc]);
            uint32_t va2 = __float_as_uint(sV[(d0w + lg) * VSTR + kc + 4]);
            uint32_t va3 = __float_as_uint(sV[(d0w + 8 + lg) * VSTR + kc + 4]);
            #pragma unroll
            for (int nt = 0; nt < 8; nt++) {
                uint32_t pb0 = __float_as_uint(sP[(nt * 8 + lg) * PSTR + kc]);
                uint32_t pb1 = __float_as_uint(sP[(nt * 8 + lg) * PSTR + kc + 4]);
                mma_tf32(Oc[nt], va0, va1, va2, va3, pb0, pb1);
            }
        }
        __syncthreads();                 // all warps done reading V_i

        // issue V(i+1)
        if (i + 1 < NTILE) {
            int m1 = m0 + 32;
            #pragma unroll
            for (int j = 0; j < 4; j++) {
                int d = vd0 + j * 32;
                cp16(sV + d * VSTR + vch, VB + (size_t)d * NN + m1 + vch);
            }
        }
        cp_commit();                     // {K_{i+1}, V_{i+1}}
    }

    // ---- fold row sums
    rsum0 += __shfl_xor_sync(0xffffffffu, rsum0, 1);
    rsum0 += __shfl_xor_sync(0xffffffffu, rsum0, 2);
    rsum1 += __shfl_xor_sync(0xffffffffu, rsum1, 1);
    rsum1 += __shfl_xor_sync(0xffffffffu, rsum1, 2);
    if (lt == 0) {
        atomicAdd(&sSum[qrS], rsum0);
        atomicAdd(&sSum[qrS + 8], rsum1);
    }
    __syncthreads();
    if (tid < 64) sSum[tid] = 1.0f / sSum[tid];
    __syncthreads();

    // ---- store relu(rna(o)) as [d][q], coalesced float2
    float* XXb = XX + ((size_t)b * DHCH + h * DDIM) * NN;
    #pragma unroll
    for (int nt = 0; nt < 8; nt++) {
        int qc = nt * 8 + 2 * lt;
        float i0 = sSum[qc], i1 = sSum[qc + 1];
        float o00 = rn_tf32(fmaxf(Oc[nt][0] * i0, 0.f));
        float o01 = rn_tf32(fmaxf(Oc[nt][1] * i1, 0.f));
        float o10 = rn_tf32(fmaxf(Oc[nt][2] * i0, 0.f));
        float o11 = rn_tf32(fmaxf(Oc[nt][3] * i1, 0.f));
        *(float2*)&XXb[(size_t)(d0w + lg) * NN + n0 + qc]     = make_float2(o00, o01);
        *(float2*)&XXb[(size_t)(d0w + 8 + lg) * NN + n0 + qc] = make_float2(o10, o11);
    }
}

// ---------------------------------------------------------------------------
extern "C" void kernel_launch(void* const* d_in, const int* in_sizes, int n_in,
                              void* d_out, int out_size)
{
    const float* x  = (const float*)d_in[0];
    const float* wq = (const float*)d_in[1];
    const float* gq = (const float*)d_in[2];
    const float* bq = (const float*)d_in[3];
    const float* wk = (const float*)d_in[4];
    const float* gk = (const float*)d_in[5];
    const float* bk = (const float*)d_in[6];
    const float* wv = (const float*)d_in[7];
    const float* gv = (const float*)d_in[8];
    const float* bv = (const float*)d_in[9];
    const float* wp = (const float*)d_in[10];
    const float* gp = (const float*)d_in[11];
    const float* bp = (const float*)d_in[12];
    float* out = (float*)d_out;

    float *xr, *qh, *ql, *kh, *kl, *v, *xx;
    float *wqh, *wql, *wkh, *wkl, *wvh, *wvl, *wph, *wpl;
    cudaGetSymbolAddress((void**)&xr,  g_xr);
    cudaGetSymbolAddress((void**)&qh,  g_qh);
    cudaGetSymbolAddress((void**)&ql,  g_ql);
    cudaGetSymbolAddress((void**)&kh,  g_kh);
    cudaGetSymbolAddress((void**)&kl,  g_kl);
    cudaGetSymbolAddress((void**)&v,   g_v);
    cudaGetSymbolAddress((void**)&xx,  g_xx);
    cudaGetSymbolAddress((void**)&wqh, g_wqh);
    cudaGetSymbolAddress((void**)&wql, g_wql);
    cudaGetSymbolAddress((void**)&wkh, g_wkh);
    cudaGetSymbolAddress((void**)&wkl, g_wkl);
    cudaGetSymbolAddress((void**)&wvh, g_wvh);
    cudaGetSymbolAddress((void**)&wvl, g_wvl);
    cudaGetSymbolAddress((void**)&wph, g_wph);
    cudaGetSymbolAddress((void**)&wpl, g_wpl);

    dim3 blk(256);

    // prep: round x, split weights
    round_tf32_kernel<<<1024, 256>>>(x, xr, BB * CCH * NN);
    split_tf32_kernel<<<256, 256>>>(wq, wqh, wql, CCH * CCH);
    split_tf32_kernel<<<256, 256>>>(wk, wkh, wkl, CCH * CCH);
    split_tf32_kernel<<<512, 256>>>(wv, wvh, wvl, DHCH * CCH);
    split_tf32_kernel<<<512, 256>>>(wp, wph, wpl, CCH * DHCH);

    // projections (tf32 mma)
    proj_mma_kernel<<<dim3(NN / 64, CCH / 64,  BB), blk>>>(xr, wqh, wql, gq, bq, qh, ql, CCH, CCH, 1);
    proj_mma_kernel<<<dim3(NN / 64, CCH / 64,  BB), blk>>>(xr, wkh, wkl, gk, bk, kh, kl, CCH, CCH, 1);
    proj_mma_kernel<<<dim3(NN / 64, DHCH / 64, BB), blk>>>(xr, wvh, wvl, gv, bv, v,  v,  CCH, DHCH, 2);

    // fused attention (writes relu(rna(o)))
    attn_mma_kernel<<<dim3(NN / 64, NHEAD, BB), blk>>>(qh, ql, kh, kl, v, xx);

    // output projection (pure GEMM + BN)
    proj_mma_kernel<<<dim3(NN / 64, CCH / 64, BB), blk>>>(xx, wph, wpl, gp, bp, out, out, DHCH, CCH, 0);
}

// round 6
// speedup vs baseline: 3.1498x; 1.0371x over previous
#include <cuda_runtime.h>
#include <math_constants.h>
#include <cstdint>

#define EPSV 1e-5f

// Problem constants
#define NN    2304
#define NHEAD 8
#define KDIM  32
#define DDIM  128
#define CCH   256
#define DHCH  1024
#define BB    4

// Scratch (allocation-free rule: device globals)
__device__ float g_qh[BB * CCH * NN];
__device__ float g_ql[BB * CCH * NN];
__device__ float g_kh[BB * CCH * NN];
__device__ float g_kl[BB * CCH * NN];
__device__ float g_v [BB * DHCH * NN];    // tf32-rounded V
__device__ float g_xx[BB * DHCH * NN];    // relu(rna(attn out)) -- tf32 values
__device__ float g_wqh[CCH * CCH],  g_wql[CCH * CCH];
__device__ float g_wkh[CCH * CCH],  g_wkl[CCH * CCH];
__device__ float g_wvh[DHCH * CCH], g_wvl[DHCH * CCH];
__device__ float g_wph[CCH * DHCH], g_wpl[CCH * DHCH];

// ---------------------------------------------------------------------------
// helpers
// ---------------------------------------------------------------------------
__device__ __forceinline__ uint32_t f2tf32(float x) {
    uint32_t r;
    asm("cvt.rna.tf32.f32 %0, %1;" : "=r"(r) : "f"(x));
    return r;
}
__device__ __forceinline__ float rn_tf32(float x) {
    return __uint_as_float(f2tf32(x));
}

__device__ __forceinline__ void mma_tf32(float c[4], uint32_t a0, uint32_t a1,
                                         uint32_t a2, uint32_t a3,
                                         uint32_t b0, uint32_t b1) {
    asm volatile(
        "mma.sync.aligned.m16n8k8.row.col.f32.tf32.tf32.f32 "
        "{%0,%1,%2,%3}, {%4,%5,%6,%7}, {%8,%9}, {%0,%1,%2,%3};\n"
        : "+f"(c[0]), "+f"(c[1]), "+f"(c[2]), "+f"(c[3])
        : "r"(a0), "r"(a1), "r"(a2), "r"(a3), "r"(b0), "r"(b1));
}

__device__ __forceinline__ void cp16(void* sdst, const void* gsrc) {
    uint32_t s = (uint32_t)__cvta_generic_to_shared(sdst);
    asm volatile("cp.async.ca.shared.global [%0], [%1], 16;" :: "r"(s), "l"(gsrc));
}
__device__ __forceinline__ void cp_commit() {
    asm volatile("cp.async.commit_group;");
}
template <int N>
__device__ __forceinline__ void cp_wait() {
    asm volatile("cp.async.wait_group %0;" :: "n"(N));
}

// exp on the FMA pipe (no MUFU). |rel err| ~2e-6 for |x| < 30.
__device__ __forceinline__ float fast_exp(float x) {
    float t = x * 1.4426950408889634f;
    float r = rintf(t);
    float f = t - r;
    float p = 0.0013333558f;
    p = fmaf(p, f, 0.0096181291f);
    p = fmaf(p, f, 0.0555041086f);
    p = fmaf(p, f, 0.2402265069f);
    p = fmaf(p, f, 0.6931471806f);
    p = fmaf(p, f, 1.0f);
    int e = (__float2int_rn(r) + 127) << 23;
    return p * __int_as_float(e);
}

// ---------------------------------------------------------------------------
// Prep: split all four weight matrices into tf32 hi/lo. blockIdx.y = task.
// ---------------------------------------------------------------------------
__global__ void prep_split_kernel(const float* __restrict__ wq, const float* __restrict__ wk,
                                  const float* __restrict__ wv, const float* __restrict__ wp,
                                  float* __restrict__ wqh, float* __restrict__ wql,
                                  float* __restrict__ wkh, float* __restrict__ wkl,
                                  float* __restrict__ wvh, float* __restrict__ wvl,
                                  float* __restrict__ wph, float* __restrict__ wpl)
{
    const float* src; float* h; float* l; int n;
    switch (blockIdx.y) {
        case 0:  src = wq; h = wqh; l = wql; n = CCH * CCH;  break;
        case 1:  src = wk; h = wkh; l = wkl; n = CCH * CCH;  break;
        case 2:  src = wv; h = wvh; l = wvl; n = DHCH * CCH; break;
        default: src = wp; h = wph; l = wpl; n = CCH * DHCH; break;
    }
    for (int i = blockIdx.x * blockDim.x + threadIdx.x; i < n; i += gridDim.x * blockDim.x) {
        float v = src[i];
        float hv = rn_tf32(v);
        h[i] = hv;
        l[i] = v - hv;
    }
}

// ---------------------------------------------------------------------------
// Shared GEMM body for projections (tf32 mma + BN), as a template-ish device fn.
// W split hi/lo (exact). X: fp32; rounded to tf32 at fragment load when rndX=1
// (Q/K/V path reads raw x), or already tf32 (final path, rndX=0).
// mode 0: plain store. mode 1: split store (Y0 hi, Y1 lo). mode 2: rounded store.
// ---------------------------------------------------------------------------
#define WSTR 20
#define XSTR 68
__device__ __forceinline__ void proj_body(
    const float* __restrict__ Xb,   // X base for this batch [C][NN]
    const float* __restrict__ Wh, const float* __restrict__ Wl,
    const float* __restrict__ gbn, const float* __restrict__ bbn,
    float* __restrict__ Y0, float* __restrict__ Y1,
    int C, int O, int mode, int rndX,
    int b, int o0, int n0,
    float* sWhP, float* sWlP, float* sXP)   // smem: 2x64*WSTR, 2x64*WSTR, 2x16*XSTR
{
    const int tid = threadIdx.x;
    const int lane = tid & 31;
    const int w  = tid >> 5;
    const int lg = lane >> 2;
    const int lt = lane & 3;
    const int ow = (w & 3) * 16;
    const int nw = (w >> 2) * 32;

    const int wlo = tid >> 2, wlc = (tid & 3) * 4;
    const int xlc = tid >> 4, xln = (tid & 15) * 4;

    const int steps = C / 16;

    cp16(&sWhP[wlo * WSTR + wlc], Wh + (size_t)(o0 + wlo) * C + wlc);
    cp16(&sWlP[wlo * WSTR + wlc], Wl + (size_t)(o0 + wlo) * C + wlc);
    cp16(&sXP [xlc * XSTR + xln], Xb + (size_t)xlc * NN + n0 + xln);
    cp_commit();

    float Oc[4][4];
    #pragma unroll
    for (int nt = 0; nt < 4; nt++)
        #pragma unroll
        for (int j = 0; j < 4; j++) Oc[nt][j] = 0.f;

    for (int s = 0; s < steps; s++) {
        const int cur = s & 1, nxt = cur ^ 1;
        float* sWh = sWhP + cur * 64 * WSTR;
        float* sWl = sWlP + cur * 64 * WSTR;
        float* sX  = sXP  + cur * 16 * XSTR;
        if (s + 1 < steps) {
            int c0 = (s + 1) * 16;
            cp16(&sWhP[nxt * 64 * WSTR + wlo * WSTR + wlc], Wh + (size_t)(o0 + wlo) * C + c0 + wlc);
            cp16(&sWlP[nxt * 64 * WSTR + wlo * WSTR + wlc], Wl + (size_t)(o0 + wlo) * C + c0 + wlc);
            cp16(&sXP [nxt * 16 * XSTR + xlc * XSTR + xln], Xb + (size_t)(c0 + xlc) * NN + n0 + xln);
        }
        cp_commit();
        cp_wait<1>();
        __syncthreads();

        #pragma unroll
        for (int kk = 0; kk < 2; kk++) {
            int kc = kk * 8 + lt;
            uint32_t ah0 = __float_as_uint(sWh[(ow + lg) * WSTR + kc]);
            uint32_t ah1 = __float_as_uint(sWh[(ow + 8 + lg) * WSTR + kc]);
            uint32_t ah2 = __float_as_uint(sWh[(ow + lg) * WSTR + kc + 4]);
            uint32_t ah3 = __float_as_uint(sWh[(ow + 8 + lg) * WSTR + kc + 4]);
            uint32_t al0 = __float_as_uint(sWl[(ow + lg) * WSTR + kc]);
            uint32_t al1 = __float_as_uint(sWl[(ow + 8 + lg) * WSTR + kc]);
            uint32_t al2 = __float_as_uint(sWl[(ow + lg) * WSTR + kc + 4]);
            uint32_t al3 = __float_as_uint(sWl[(ow + 8 + lg) * WSTR + kc + 4]);
            #pragma unroll
            for (int nt = 0; nt < 4; nt++) {
                int nc = nw + nt * 8 + lg;
                float x0 = sX[kc * XSTR + nc];
                float x1 = sX[(kc + 4) * XSTR + nc];
                uint32_t b0 = rndX ? f2tf32(x0) : __float_as_uint(x0);
                uint32_t b1 = rndX ? f2tf32(x1) : __float_as_uint(x1);
                mma_tf32(Oc[nt], ah0, ah1, ah2, ah3, b0, b1);
                mma_tf32(Oc[nt], al0, al1, al2, al3, b0, b1);
            }
        }
        __syncthreads();
    }

    const float rs = rsqrtf(1.f + EPSV);
    const int oa = o0 + ow + lg;
    const int ob = oa + 8;
    const float sa = gbn[oa] * rs, ba = bbn[oa];
    const float sb = gbn[ob] * rs, bb2 = bbn[ob];

    #pragma unroll
    for (int nt = 0; nt < 4; nt++) {
        int n = n0 + nw + nt * 8 + 2 * lt;
        float ya0 = Oc[nt][0] * sa + ba;
        float ya1 = Oc[nt][1] * sa + ba;
        float yb0 = Oc[nt][2] * sb + bb2;
        float yb1 = Oc[nt][3] * sb + bb2;
        size_t ia = ((size_t)b * O + oa) * NN + n;
        size_t ib = ((size_t)b * O + ob) * NN + n;
        if (mode == 0) {
            *(float2*)&Y0[ia] = make_float2(ya0, ya1);
            *(float2*)&Y0[ib] = make_float2(yb0, yb1);
        } else if (mode == 1) {
            float ha0 = rn_tf32(ya0), ha1 = rn_tf32(ya1);
            float hb0 = rn_tf32(yb0), hb1 = rn_tf32(yb1);
            *(float2*)&Y0[ia] = make_float2(ha0, ha1);
            *(float2*)&Y0[ib] = make_float2(hb0, hb1);
            *(float2*)&Y1[ia] = make_float2(ya0 - ha0, ya1 - ha1);
            *(float2*)&Y1[ib] = make_float2(yb0 - hb0, yb1 - hb1);
        } else {
            *(float2*)&Y0[ia] = make_float2(rn_tf32(ya0), rn_tf32(ya1));
            *(float2*)&Y0[ib] = make_float2(rn_tf32(yb0), rn_tf32(yb1));
        }
    }
}

// Fused Q/K/V projection: blockIdx.y segments (0-3 Q, 4-7 K, 8-23 V)
__global__ __launch_bounds__(256, 3)
void proj_qkv_kernel(const float* __restrict__ x,
                     const float* __restrict__ wqh, const float* __restrict__ wql,
                     const float* __restrict__ gq,  const float* __restrict__ bq,
                     const float* __restrict__ wkh, const float* __restrict__ wkl,
                     const float* __restrict__ gk,  const float* __restrict__ bk,
                     const float* __restrict__ wvh, const float* __restrict__ wvl,
                     const float* __restrict__ gv,  const float* __restrict__ bv,
                     float* __restrict__ qh, float* __restrict__ ql,
                     float* __restrict__ kh, float* __restrict__ kl,
                     float* __restrict__ v)
{
    __shared__ __align__(16) float sWh[2 * 64 * WSTR];
    __shared__ __align__(16) float sWl[2 * 64 * WSTR];
    __shared__ __align__(16) float sX [2 * 16 * XSTR];

    const int seg = blockIdx.y;
    const int b   = blockIdx.z;
    const int n0  = blockIdx.x * 64;

    const float* Wh; const float* Wl; const float* g; const float* be;
    float* Y0; float* Y1; int O, mode, o0;
    if (seg < 4)      { Wh = wqh; Wl = wql; g = gq; be = bq; Y0 = qh; Y1 = ql; O = CCH;  mode = 1; o0 = seg * 64; }
    else if (seg < 8) { Wh = wkh; Wl = wkl; g = gk; be = bk; Y0 = kh; Y1 = kl; O = CCH;  mode = 1; o0 = (seg - 4) * 64; }
    else              { Wh = wvh; Wl = wvl; g = gv; be = bv; Y0 = v;  Y1 = v;  O = DHCH; mode = 2; o0 = (seg - 8) * 64; }

    proj_body(x + (size_t)b * CCH * NN, Wh, Wl, g, be, Y0, Y1,
              CCH, O, mode, /*rndX=*/1, b, o0, n0, sWh, sWl, sX);
}

// Final projection (C=1024, X already tf32 values)
__global__ __launch_bounds__(256, 3)
void proj_out_kernel(const float* __restrict__ xx,
                     const float* __restrict__ wph, const float* __restrict__ wpl,
                     const float* __restrict__ gp,  const float* __restrict__ bp,
                     float* __restrict__ out)
{
    __shared__ __align__(16) float sWh[2 * 64 * WSTR];
    __shared__ __align__(16) float sWl[2 * 64 * WSTR];
    __shared__ __align__(16) float sX [2 * 16 * XSTR];

    const int b  = blockIdx.z;
    const int o0 = blockIdx.y * 64;
    const int n0 = blockIdx.x * 64;

    proj_body(xx + (size_t)b * DHCH * NN, wph, wpl, gp, bp, out, out,
              DHCH, CCH, /*mode=*/0, /*rndX=*/0, b, o0, n0, sWh, sWl, sX);
}

// ---------------------------------------------------------------------------
// Tensor-core fused attention. 2 barriers per key-tile.
//   TQ=64 q/block, TM=32 keys/tile, 256 threads.
//   K hi/lo [kd][m] stride 40, double-buffered cp.async.
//   V [d][m] stride 36, single-buffered: each warp hoists its 16 V fragments
//   to registers before the P-barrier, so V(i+1) cp.async issues right after
//   it and is hidden under the PV phase.
// pool (floats): kh0@0 kl0@1280 kh1@2560 kl1@3840 (each 32*40)
//                V@5120 (128*36=4608)  P@9728 (64*36=2304)  sums@12032 (64)
// prologue staging: Qh in P region, Ql @2560 (K buf B region)
// ---------------------------------------------------------------------------
#define KSTR 40
#define VSTR 36
#define PSTR 36
#define POOL_FLOATS 12096

__global__ __launch_bounds__(256, 2)
void attn_mma_kernel(const float* __restrict__ Qh, const float* __restrict__ Ql,
                     const float* __restrict__ Kh, const float* __restrict__ Kl,
                     const float* __restrict__ V, float* __restrict__ XX)
{
    __shared__ __align__(16) float pool[POOL_FLOATS];
    float* sKh0 = pool;
    float* sKl0 = pool + 1280;
    float* sKh1 = pool + 2560;
    float* sKl1 = pool + 3840;
    float* sV   = pool + 5120;
    float* sP   = pool + 9728;
    float* sSum = pool + 12032;
    float* stQh = sP;            // prologue staging (64*36)
    float* stQl = pool + 2560;   // prologue staging (64*36 <= 2560 region+)

    const int tid  = threadIdx.x;
    const int lane = tid & 31;
    const int w    = tid >> 5;
    const int lg   = lane >> 2;
    const int lt   = lane & 3;

    const int n0 = blockIdx.x * 64;
    const int h  = blockIdx.y;
    const int b  = blockIdx.z;

    const float* QhB = Qh + ((size_t)b * CCH + h * KDIM) * NN;
    const float* QlB = Ql + ((size_t)b * CCH + h * KDIM) * NN;
    const float* KhB = Kh + ((size_t)b * CCH + h * KDIM) * NN;
    const float* KlB = Kl + ((size_t)b * CCH + h * KDIM) * NN;
    const float* VB  = V  + ((size_t)b * DHCH + h * DDIM) * NN;

    // cp.async thread mapping for K (32kd x 32m) and V (128d x 32m)
    const int kkd = tid >> 3;            // 0..31
    const int kch = (tid & 7) * 4;       // m offset
    const int vd0 = tid >> 3;            // + j*32
    const int vch = (tid & 7) * 4;

    // ---- prologue: issue K0 + V0 together (V region untouched by staging)
    cp16(sKh0 + kkd * KSTR + kch, KhB + (size_t)kkd * NN + kch);
    cp16(sKl0 + kkd * KSTR + kch, KlB + (size_t)kkd * NN + kch);
    #pragma unroll
    for (int j = 0; j < 4; j++) {
        int d = vd0 + j * 32;
        cp16(sV + d * VSTR + vch, VB + (size_t)d * NN + vch);
    }
    cp_commit();

    // ---- stage Q (coalesced over q) into P + KbufB regions, init sums
    #pragma unroll
    for (int i = 0; i < 8; i++) {
        int t = tid + i * 256;
        int kd = t >> 6, q = t & 63;
        stQh[q * 36 + kd] = QhB[(size_t)kd * NN + n0 + q];
        stQl[q * 36 + kd] = QlB[(size_t)kd * NN + n0 + q];
    }
    if (tid < 64) sSum[tid] = 0.f;
    __syncthreads();

    // ---- hoist Q A-fragments
    const int qrS = (w & 3) * 16 + lg;
    uint32_t ah[4][4], al[4][4];
    #pragma unroll
    for (int kt = 0; kt < 4; kt++) {
        int c0 = kt * 8 + lt;
        ah[kt][0] = __float_as_uint(stQh[qrS * 36 + c0]);
        ah[kt][1] = __float_as_uint(stQh[(qrS + 8) * 36 + c0]);
        ah[kt][2] = __float_as_uint(stQh[qrS * 36 + c0 + 4]);
        ah[kt][3] = __float_as_uint(stQh[(qrS + 8) * 36 + c0 + 4]);
        al[kt][0] = __float_as_uint(stQl[qrS * 36 + c0]);
        al[kt][1] = __float_as_uint(stQl[(qrS + 8) * 36 + c0]);
        al[kt][2] = __float_as_uint(stQl[qrS * 36 + c0 + 4]);
        al[kt][3] = __float_as_uint(stQl[(qrS + 8) * 36 + c0 + 4]);
    }
    __syncthreads();   // staging regions (P, KbufB) now free

    float Oc[8][4];
    #pragma unroll
    for (int nt = 0; nt < 8; nt++)
        #pragma unroll
        for (int j = 0; j < 4; j++) Oc[nt][j] = 0.f;

    float rsum0 = 0.f, rsum1 = 0.f;
    const int n0w = (w >> 2) * 16;
    const int d0w = w * 16;

    const int NTILE = NN / 32;           // 72
    for (int i = 0; i < NTILE; i++) {
        // wait K_i + V_i (everything committed so far)
        cp_wait<0>();
        __syncthreads();                              // [sync1]

        float* curKh = (i & 1) ? sKh1 : sKh0;
        float* curKl = (i & 1) ? sKl1 : sKl0;
        float* nxtKh = (i & 1) ? sKh0 : sKh1;
        float* nxtKl = (i & 1) ? sKl0 : sKl1;

        // issue K(i+1) into the other buffer (free since S(i-1) completed)
        if (i + 1 < NTILE) {
            int m1 = (i + 1) * 32;
            cp16(nxtKh + kkd * KSTR + kch, KhB + (size_t)kkd * NN + m1 + kch);
            cp16(nxtKl + kkd * KSTR + kch, KlB + (size_t)kkd * NN + m1 + kch);
        }

        // ---- S = Q K^T (3xTF32); warp: 16 q x 16 m
        float sc[2][4];
        #pragma unroll
        for (int nt = 0; nt < 2; nt++) {
            sc[nt][0] = sc[nt][1] = sc[nt][2] = sc[nt][3] = 0.f;
            int mc = n0w + nt * 8 + lg;
            #pragma unroll
            for (int kt = 0; kt < 4; kt++) {
                int kc = kt * 8 + lt;
                uint32_t bh0 = __float_as_uint(curKh[kc * KSTR + mc]);
                uint32_t bh1 = __float_as_uint(curKh[(kc + 4) * KSTR + mc]);
                uint32_t bl0 = __float_as_uint(curKl[kc * KSTR + mc]);
                uint32_t bl1 = __float_as_uint(curKl[(kc + 4) * KSTR + mc]);
                mma_tf32(sc[nt], ah[kt][0], ah[kt][1], ah[kt][2], ah[kt][3], bh0, bh1);
                mma_tf32(sc[nt], ah[kt][0], ah[kt][1], ah[kt][2], ah[kt][3], bl0, bl1);
                mma_tf32(sc[nt], al[kt][0], al[kt][1], al[kt][2], al[kt][3], bh0, bh1);
            }
        }

        // ---- hoist this warp's V_i fragments (own 16 d-rows only)
        uint32_t va[4][4];
        #pragma unroll
        for (int kt = 0; kt < 4; kt++) {
            int kc = kt * 8 + lt;
            va[kt][0] = __float_as_uint(sV[(d0w + lg) * VSTR + kc]);
            va[kt][1] = __float_as_uint(sV[(d0w + 8 + lg) * VSTR + kc]);
            va[kt][2] = __float_as_uint(sV[(d0w + lg) * VSTR + kc + 4]);
            va[kt][3] = __float_as_uint(sV[(d0w + 8 + lg) * VSTR + kc + 4]);
        }

        // ---- P = rna(exp(S)); row sums from the rounded values
        #pragma unroll
        for (int nt = 0; nt < 2; nt++) {
            float p0 = rn_tf32(fast_exp(sc[nt][0]));
            float p1 = rn_tf32(fast_exp(sc[nt][1]));
            float p2 = rn_tf32(fast_exp(sc[nt][2]));
            float p3 = rn_tf32(fast_exp(sc[nt][3]));
            rsum0 += p0 + p1;
            rsum1 += p2 + p3;
            int col = n0w + nt * 8 + 2 * lt;
            *(float2*)&sP[qrS * PSTR + col]       = make_float2(p0, p1);
            *(float2*)&sP[(qrS + 8) * PSTR + col] = make_float2(p2, p3);
        }
        __syncthreads();                              // [sync2] P visible, V hoisted

        // issue V(i+1) (overwrites V_i -- safe, all warps hoisted)
        if (i + 1 < NTILE) {
            int m1 = (i + 1) * 32;
            #pragma unroll
            for (int j = 0; j < 4; j++) {
                int d = vd0 + j * 32;
                cp16(sV + d * VSTR + vch, VB + (size_t)d * NN + m1 + vch);
            }
        }
        cp_commit();   // one group per iter: {K(i+1), V(i+1)}

        // ---- O += V * P^T; warp: 16 d x 64 q (V from regs)
        #pragma unroll
        for (int kt = 0; kt < 4; kt++) {
            int kc = kt * 8 + lt;
            #pragma unroll
            for (int nt = 0; nt < 8; nt++) {
                uint32_t pb0 = __float_as_uint(sP[(nt * 8 + lg) * PSTR + kc]);
                uint32_t pb1 = __float_as_uint(sP[(nt * 8 + lg) * PSTR + kc + 4]);
                mma_tf32(Oc[nt], va[kt][0], va[kt][1], va[kt][2], va[kt][3], pb0, pb1);
            }
        }
    }

    // ---- fold row sums
    rsum0 += __shfl_xor_sync(0xffffffffu, rsum0, 1);
    rsum0 += __shfl_xor_sync(0xffffffffu, rsum0, 2);
    rsum1 += __shfl_xor_sync(0xffffffffu, rsum1, 1);
    rsum1 += __shfl_xor_sync(0xffffffffu, rsum1, 2);
    if (lt == 0) {
        atomicAdd(&sSum[qrS], rsum0);
        atomicAdd(&sSum[qrS + 8], rsum1);
    }
    __syncthreads();
    if (tid < 64) sSum[tid] = 1.0f / sSum[tid];
    __syncthreads();

    // ---- store relu(rna(o)) as [d][q], coalesced float2
    float* XXb = XX + ((size_t)b * DHCH + h * DDIM) * NN;
    #pragma unroll
    for (int nt = 0; nt < 8; nt++) {
        int qc = nt * 8 + 2 * lt;
        float i0 = sSum[qc], i1 = sSum[qc + 1];
        float o00 = rn_tf32(fmaxf(Oc[nt][0] * i0, 0.f));
        float o01 = rn_tf32(fmaxf(Oc[nt][1] * i1, 0.f));
        float o10 = rn_tf32(fmaxf(Oc[nt][2] * i0, 0.f));
        float o11 = rn_tf32(fmaxf(Oc[nt][3] * i1, 0.f));
        *(float2*)&XXb[(size_t)(d0w + lg) * NN + n0 + qc]     = make_float2(o00, o01);
        *(float2*)&XXb[(size_t)(d0w + 8 + lg) * NN + n0 + qc] = make_float2(o10, o11);
    }
}

// ---------------------------------------------------------------------------
extern "C" void kernel_launch(void* const* d_in, const int* in_sizes, int n_in,
                              void* d_out, int out_size)
{
    const float* x  = (const float*)d_in[0];
    const float* wq = (const float*)d_in[1];
    const float* gq = (const float*)d_in[2];
    const float* bq = (const float*)d_in[3];
    const float* wk = (const float*)d_in[4];
    const float* gk = (const float*)d_in[5];
    const float* bk = (const float*)d_in[6];
    const float* wv = (const float*)d_in[7];
    const float* gv = (const float*)d_in[8];
    const float* bv = (const float*)d_in[9];
    const float* wp = (const float*)d_in[10];
    const float* gp = (const float*)d_in[11];
    const float* bp = (const float*)d_in[12];
    float* out = (float*)d_out;

    float *qh, *ql, *kh, *kl, *v, *xx;
    float *wqh, *wql, *wkh, *wkl, *wvh, *wvl, *wph, *wpl;
    cudaGetSymbolAddress((void**)&qh,  g_qh);
    cudaGetSymbolAddress((void**)&ql,  g_ql);
    cudaGetSymbolAddress((void**)&kh,  g_kh);
    cudaGetSymbolAddress((void**)&kl,  g_kl);
    cudaGetSymbolAddress((void**)&v,   g_v);
    cudaGetSymbolAddress((void**)&xx,  g_xx);
    cudaGetSymbolAddress((void**)&wqh, g_wqh);
    cudaGetSymbolAddress((void**)&wql, g_wql);
    cudaGetSymbolAddress((void**)&wkh, g_wkh);
    cudaGetSymbolAddress((void**)&wkl, g_wkl);
    cudaGetSymbolAddress((void**)&wvh, g_wvh);
    cudaGetSymbolAddress((void**)&wvl, g_wvl);
    cudaGetSymbolAddress((void**)&wph, g_wph);
    cudaGetSymbolAddress((void**)&wpl, g_wpl);

    // 1) split weights (one launch)
    prep_split_kernel<<<dim3(160, 4), 256>>>(wq, wk, wv, wp,
                                             wqh, wql, wkh, wkl,
                                             wvh, wvl, wph, wpl);

    // 2) fused Q/K/V projections (x rounded at fragment load)
    proj_qkv_kernel<<<dim3(NN / 64, 24, BB), 256>>>(x,
        wqh, wql, gq, bq, wkh, wkl, gk, bk, wvh, wvl, gv, bv,
        qh, ql, kh, kl, v);

    // 3) fused attention
    attn_mma_kernel<<<dim3(NN / 64, NHEAD, BB), 256>>>(qh, ql, kh, kl, v, xx);

    // 4) output projection + BN
    proj_out_kernel<<<dim3(NN / 64, CCH / 64, BB), 256>>>(xx, wph, wpl, gp, bp, out);
}

// round 7
// speedup vs baseline: 3.4717x; 1.1022x over previous
#include <cuda_runtime.h>
#include <cuda_bf16.h>
#include <math_constants.h>
#include <cstdint>

#define EPSV 1e-5f

// Problem constants
#define NN    2304
#define NHEAD 8
#define KDIM  32
#define DDIM  128
#define CCH   256
#define DHCH  1024
#define BB    4

// Scratch (allocation-free rule: device globals)
__device__ __nv_bfloat16 g_qh[BB * CCH * NN];   // Q bf16 hi
__device__ __nv_bfloat16 g_ql[BB * CCH * NN];   // Q bf16 lo
__device__ __nv_bfloat16 g_kh[BB * CCH * NN];   // K bf16 hi
__device__ __nv_bfloat16 g_kl[BB * CCH * NN];   // K bf16 lo
__device__ float g_v [BB * DHCH * NN];          // tf32-rounded V
__device__ float g_xx[BB * DHCH * NN];          // relu(rna(attn out))
__device__ float g_wqh[CCH * CCH],  g_wql[CCH * CCH];
__device__ float g_wkh[CCH * CCH],  g_wkl[CCH * CCH];
__device__ float g_wvh[DHCH * CCH], g_wvl[DHCH * CCH];
__device__ float g_wph[CCH * DHCH], g_wpl[CCH * DHCH];

// ---------------------------------------------------------------------------
// helpers
// ---------------------------------------------------------------------------
__device__ __forceinline__ uint32_t f2tf32(float x) {
    uint32_t r;
    asm("cvt.rna.tf32.f32 %0, %1;" : "=r"(r) : "f"(x));
    return r;
}
__device__ __forceinline__ float rn_tf32(float x) {
    return __uint_as_float(f2tf32(x));
}

__device__ __forceinline__ void mma_tf32(float c[4], uint32_t a0, uint32_t a1,
                                         uint32_t a2, uint32_t a3,
                                         uint32_t b0, uint32_t b1) {
    asm volatile(
        "mma.sync.aligned.m16n8k8.row.col.f32.tf32.tf32.f32 "
        "{%0,%1,%2,%3}, {%4,%5,%6,%7}, {%8,%9}, {%0,%1,%2,%3};\n"
        : "+f"(c[0]), "+f"(c[1]), "+f"(c[2]), "+f"(c[3])
        : "r"(a0), "r"(a1), "r"(a2), "r"(a3), "r"(b0), "r"(b1));
}

__device__ __forceinline__ void mma_bf16(float c[4], const uint32_t a[4],
                                         uint32_t b0, uint32_t b1) {
    asm volatile(
        "mma.sync.aligned.m16n8k16.row.col.f32.bf16.bf16.f32 "
        "{%0,%1,%2,%3}, {%4,%5,%6,%7}, {%8,%9}, {%0,%1,%2,%3};\n"
        : "+f"(c[0]), "+f"(c[1]), "+f"(c[2]), "+f"(c[3])
        : "r"(a[0]), "r"(a[1]), "r"(a[2]), "r"(a[3]), "r"(b0), "r"(b1));
}

__device__ __forceinline__ void ldm_x4(uint32_t r[4], uint32_t addr) {
    asm volatile("ldmatrix.sync.aligned.m8n8.x4.shared.b16 {%0,%1,%2,%3}, [%4];"
        : "=r"(r[0]), "=r"(r[1]), "=r"(r[2]), "=r"(r[3]) : "r"(addr));
}
__device__ __forceinline__ void ldm_x2t(uint32_t& r0, uint32_t& r1, uint32_t addr) {
    asm volatile("ldmatrix.sync.aligned.m8n8.x2.trans.shared.b16 {%0,%1}, [%2];"
        : "=r"(r0), "=r"(r1) : "r"(addr));
}

__device__ __forceinline__ void cp16(void* sdst, const void* gsrc) {
    uint32_t s = (uint32_t)__cvta_generic_to_shared(sdst);
    asm volatile("cp.async.ca.shared.global [%0], [%1], 16;" :: "r"(s), "l"(gsrc));
}
__device__ __forceinline__ void cp_commit() {
    asm volatile("cp.async.commit_group;");
}
template <int N>
__device__ __forceinline__ void cp_wait() {
    asm volatile("cp.async.wait_group %0;" :: "n"(N));
}

// exp on the FMA pipe (no MUFU). |rel err| ~2e-6 for |x| < 30.
__device__ __forceinline__ float fast_exp(float x) {
    float t = x * 1.4426950408889634f;
    float r = rintf(t);
    float f = t - r;
    float p = 0.0013333558f;
    p = fmaf(p, f, 0.0096181291f);
    p = fmaf(p, f, 0.0555041086f);
    p = fmaf(p, f, 0.2402265069f);
    p = fmaf(p, f, 0.6931471806f);
    p = fmaf(p, f, 1.0f);
    int e = (__float2int_rn(r) + 127) << 23;
    return p * __int_as_float(e);
}

// ---------------------------------------------------------------------------
// Prep: split all four weight matrices into tf32 hi/lo. blockIdx.y = task.
// ---------------------------------------------------------------------------
__global__ void prep_split_kernel(const float* __restrict__ wq, const float* __restrict__ wk,
                                  const float* __restrict__ wv, const float* __restrict__ wp,
                                  float* __restrict__ wqh, float* __restrict__ wql,
                                  float* __restrict__ wkh, float* __restrict__ wkl,
                                  float* __restrict__ wvh, float* __restrict__ wvl,
                                  float* __restrict__ wph, float* __restrict__ wpl)
{
    const float* src; float* h; float* l; int n;
    switch (blockIdx.y) {
        case 0:  src = wq; h = wqh; l = wql; n = CCH * CCH;  break;
        case 1:  src = wk; h = wkh; l = wkl; n = CCH * CCH;  break;
        case 2:  src = wv; h = wvh; l = wvl; n = DHCH * CCH; break;
        default: src = wp; h = wph; l = wpl; n = CCH * DHCH; break;
    }
    for (int i = blockIdx.x * blockDim.x + threadIdx.x; i < n; i += gridDim.x * blockDim.x) {
        float v = src[i];
        float hv = rn_tf32(v);
        h[i] = hv;
        l[i] = v - hv;
    }
}

// ---------------------------------------------------------------------------
// Shared GEMM body for projections (tf32 mma + BN).
// mode 0: plain fp32 store. mode 1: bf16 hi/lo split store (Yh, Yl).
// mode 2: tf32-rounded fp32 store.
// ---------------------------------------------------------------------------
#define WSTR 20
#define XSTR 68
__device__ __forceinline__ void proj_body(
    const float* __restrict__ Xb,
    const float* __restrict__ Wh, const float* __restrict__ Wl,
    const float* __restrict__ gbn, const float* __restrict__ bbn,
    float* __restrict__ Y0, __nv_bfloat16* __restrict__ Yh, __nv_bfloat16* __restrict__ Yl,
    int C, int O, int mode, int rndX,
    int b, int o0, int n0,
    float* sWhP, float* sWlP, float* sXP)
{
    const int tid = threadIdx.x;
    const int lane = tid & 31;
    const int w  = tid >> 5;
    const int lg = lane >> 2;
    const int lt = lane & 3;
    const int ow = (w & 3) * 16;
    const int nw = (w >> 2) * 32;

    const int wlo = tid >> 2, wlc = (tid & 3) * 4;
    const int xlc = tid >> 4, xln = (tid & 15) * 4;

    const int steps = C / 16;

    cp16(&sWhP[wlo * WSTR + wlc], Wh + (size_t)(o0 + wlo) * C + wlc);
    cp16(&sWlP[wlo * WSTR + wlc], Wl + (size_t)(o0 + wlo) * C + wlc);
    cp16(&sXP [xlc * XSTR + xln], Xb + (size_t)xlc * NN + n0 + xln);
    cp_commit();

    float Oc[4][4];
    #pragma unroll
    for (int nt = 0; nt < 4; nt++)
        #pragma unroll
        for (int j = 0; j < 4; j++) Oc[nt][j] = 0.f;

    for (int s = 0; s < steps; s++) {
        const int cur = s & 1, nxt = cur ^ 1;
        float* sWh = sWhP + cur * 64 * WSTR;
        float* sWl = sWlP + cur * 64 * WSTR;
        float* sX  = sXP  + cur * 16 * XSTR;
        if (s + 1 < steps) {
            int c0 = (s + 1) * 16;
            cp16(&sWhP[nxt * 64 * WSTR + wlo * WSTR + wlc], Wh + (size_t)(o0 + wlo) * C + c0 + wlc);
            cp16(&sWlP[nxt * 64 * WSTR + wlo * WSTR + wlc], Wl + (size_t)(o0 + wlo) * C + c0 + wlc);
            cp16(&sXP [nxt * 16 * XSTR + xlc * XSTR + xln], Xb + (size_t)(c0 + xlc) * NN + n0 + xln);
        }
        cp_commit();
        cp_wait<1>();
        __syncthreads();

        #pragma unroll
        for (int kk = 0; kk < 2; kk++) {
            int kc = kk * 8 + lt;
            uint32_t ah0 = __float_as_uint(sWh[(ow + lg) * WSTR + kc]);
            uint32_t ah1 = __float_as_uint(sWh[(ow + 8 + lg) * WSTR + kc]);
            uint32_t ah2 = __float_as_uint(sWh[(ow + lg) * WSTR + kc + 4]);
            uint32_t ah3 = __float_as_uint(sWh[(ow + 8 + lg) * WSTR + kc + 4]);
            uint32_t al0 = __float_as_uint(sWl[(ow + lg) * WSTR + kc]);
            uint32_t al1 = __float_as_uint(sWl[(ow + 8 + lg) * WSTR + kc]);
            uint32_t al2 = __float_as_uint(sWl[(ow + lg) * WSTR + kc + 4]);
            uint32_t al3 = __float_as_uint(sWl[(ow + 8 + lg) * WSTR + kc + 4]);
            #pragma unroll
            for (int nt = 0; nt < 4; nt++) {
                int nc = nw + nt * 8 + lg;
                float x0 = sX[kc * XSTR + nc];
                float x1 = sX[(kc + 4) * XSTR + nc];
                uint32_t b0 = rndX ? f2tf32(x0) : __float_as_uint(x0);
                uint32_t b1 = rndX ? f2tf32(x1) : __float_as_uint(x1);
                mma_tf32(Oc[nt], ah0, ah1, ah2, ah3, b0, b1);
                mma_tf32(Oc[nt], al0, al1, al2, al3, b0, b1);
            }
        }
        __syncthreads();
    }

    const float rs = rsqrtf(1.f + EPSV);
    const int oa = o0 + ow + lg;
    const int ob = oa + 8;
    const float sa = gbn[oa] * rs, ba = bbn[oa];
    const float sb = gbn[ob] * rs, bb2 = bbn[ob];

    #pragma unroll
    for (int nt = 0; nt < 4; nt++) {
        int n = n0 + nw + nt * 8 + 2 * lt;
        float ya0 = Oc[nt][0] * sa + ba;
        float ya1 = Oc[nt][1] * sa + ba;
        float yb0 = Oc[nt][2] * sb + bb2;
        float yb1 = Oc[nt][3] * sb + bb2;
        size_t ia = ((size_t)b * O + oa) * NN + n;
        size_t ib = ((size_t)b * O + ob) * NN + n;
        if (mode == 0) {
            *(float2*)&Y0[ia] = make_float2(ya0, ya1);
            *(float2*)&Y0[ib] = make_float2(yb0, yb1);
        } else if (mode == 1) {
            __nv_bfloat162 ha, hb, la, lb;
            ha.x = __float2bfloat16_rn(ya0);
            ha.y = __float2bfloat16_rn(ya1);
            hb.x = __float2bfloat16_rn(yb0);
            hb.y = __float2bfloat16_rn(yb1);
            la.x = __float2bfloat16_rn(ya0 - __bfloat162float(ha.x));
            la.y = __float2bfloat16_rn(ya1 - __bfloat162float(ha.y));
            lb.x = __float2bfloat16_rn(yb0 - __bfloat162float(hb.x));
            lb.y = __float2bfloat16_rn(yb1 - __bfloat162float(hb.y));
            *(__nv_bfloat162*)&Yh[ia] = ha;
            *(__nv_bfloat162*)&Yh[ib] = hb;
            *(__nv_bfloat162*)&Yl[ia] = la;
            *(__nv_bfloat162*)&Yl[ib] = lb;
        } else {
            *(float2*)&Y0[ia] = make_float2(rn_tf32(ya0), rn_tf32(ya1));
            *(float2*)&Y0[ib] = make_float2(rn_tf32(yb0), rn_tf32(yb1));
        }
    }
}

// Fused Q/K/V projection: blockIdx.y segments (0-3 Q, 4-7 K, 8-23 V)
__global__ __launch_bounds__(256, 3)
void proj_qkv_kernel(const float* __restrict__ x,
                     const float* __restrict__ wqh, const float* __restrict__ wql,
                     const float* __restrict__ gq,  const float* __restrict__ bq,
                     const float* __restrict__ wkh, const float* __restrict__ wkl,
                     const float* __restrict__ gk,  const float* __restrict__ bk,
                     const float* __restrict__ wvh, const float* __restrict__ wvl,
                     const float* __restrict__ gv,  const float* __restrict__ bv,
                     __nv_bfloat16* __restrict__ qh, __nv_bfloat16* __restrict__ ql,
                     __nv_bfloat16* __restrict__ kh, __nv_bfloat16* __restrict__ kl,
                     float* __restrict__ v)
{
    __shared__ __align__(16) float sWh[2 * 64 * WSTR];
    __shared__ __align__(16) float sWl[2 * 64 * WSTR];
    __shared__ __align__(16) float sX [2 * 16 * XSTR];

    const int seg = blockIdx.y;
    const int b   = blockIdx.z;
    const int n0  = blockIdx.x * 64;

    const float* Wh; const float* Wl; const float* g; const float* be;
    float* Y0 = nullptr; __nv_bfloat16* Yh = nullptr; __nv_bfloat16* Yl = nullptr;
    int O, mode, o0;
    if (seg < 4)      { Wh = wqh; Wl = wql; g = gq; be = bq; Yh = qh; Yl = ql; O = CCH;  mode = 1; o0 = seg * 64; }
    else if (seg < 8) { Wh = wkh; Wl = wkl; g = gk; be = bk; Yh = kh; Yl = kl; O = CCH;  mode = 1; o0 = (seg - 4) * 64; }
    else              { Wh = wvh; Wl = wvl; g = gv; be = bv; Y0 = v;  O = DHCH; mode = 2; o0 = (seg - 8) * 64; }

    proj_body(x + (size_t)b * CCH * NN, Wh, Wl, g, be, Y0, Yh, Yl,
              CCH, O, mode, /*rndX=*/1, b, o0, n0, sWh, sWl, sX);
}

// Final projection (C=1024, X already tf32 values)
__global__ __launch_bounds__(256, 3)
void proj_out_kernel(const float* __restrict__ xx,
                     const float* __restrict__ wph, const float* __restrict__ wpl,
                     const float* __restrict__ gp,  const float* __restrict__ bp,
                     float* __restrict__ out)
{
    __shared__ __align__(16) float sWh[2 * 64 * WSTR];
    __shared__ __align__(16) float sWl[2 * 64 * WSTR];
    __shared__ __align__(16) float sX [2 * 16 * XSTR];

    const int b  = blockIdx.z;
    const int o0 = blockIdx.y * 64;
    const int n0 = blockIdx.x * 64;

    proj_body(xx + (size_t)b * DHCH * NN, wph, wpl, gp, bp, out, nullptr, nullptr,
              DHCH, CCH, /*mode=*/0, /*rndX=*/0, b, o0, n0, sWh, sWl, sX);
}

// ---------------------------------------------------------------------------
// Tensor-core fused attention.
//   S = Q K^T in bf16x2 (3 bf16 m16n8k16 MMAs), frags via ldmatrix.
//   PV in tf32 (unchanged). 2 barriers per key-tile, V reg-hoisted.
// pool bytes:
//   K bufs: buf0 @0 (hi@0, lo@2560), buf1 @5120 (hi,lo)    [each 32 rows x 80B]
//   V  fp32 @10240 (128*36*4 = 18432)
//   P  fp32 @28672 (64*36*4 = 9216)
//   sums    @37888 (256)          total 38144 B
//   Q staging: Qhi @28672 (P region, 5120B), Qlo @5120 (K buf1, 5120B)
// ---------------------------------------------------------------------------
#define KSTRB 40     // bf16 units per K smem row (80 B, 16B-aligned, conflict-free)
#define QSTRB 40
#define VSTR 36
#define PSTR 36
#define POOL_BYTES 38144

__global__ __launch_bounds__(256, 2)
void attn_mma_kernel(const __nv_bfloat16* __restrict__ Qh, const __nv_bfloat16* __restrict__ Ql,
                     const __nv_bfloat16* __restrict__ Kh, const __nv_bfloat16* __restrict__ Kl,
                     const float* __restrict__ V, float* __restrict__ XX)
{
    __shared__ __align__(16) char pool[POOL_BYTES];
    float* sV   = (float*)(pool + 10240);
    float* sP   = (float*)(pool + 28672);
    float* sSum = (float*)(pool + 37888);
    __nv_bfloat16* stQh = (__nv_bfloat16*)(pool + 28672);  // prologue only
    __nv_bfloat16* stQl = (__nv_bfloat16*)(pool + 5120);   // prologue only

    const int tid  = threadIdx.x;
    const int lane = tid & 31;
    const int w    = tid >> 5;
    const int lg   = lane >> 2;
    const int lt   = lane & 3;

    const int n0 = blockIdx.x * 64;
    const int h  = blockIdx.y;
    const int b  = blockIdx.z;

    const __nv_bfloat16* QhB = Qh + ((size_t)b * CCH + h * KDIM) * NN;
    const __nv_bfloat16* QlB = Ql + ((size_t)b * CCH + h * KDIM) * NN;
    const __nv_bfloat16* KhB = Kh + ((size_t)b * CCH + h * KDIM) * NN;
    const __nv_bfloat16* KlB = Kl + ((size_t)b * CCH + h * KDIM) * NN;
    const float* VB = V + ((size_t)b * DHCH + h * DDIM) * NN;

    // cp.async maps. K: hi+lo tiles (32kd x 32m bf16): 256 threads x 16B.
    const int khalf = tid >> 7;           // 0 = hi, 1 = lo
    const int kr    = (tid & 127) >> 2;   // kd row 0..31
    const int kcol  = (tid & 3) * 8;      // m offset (8 bf16 = 16B)
    // V: 128d x 32m fp32
    const int vd0 = tid >> 3;
    const int vch = (tid & 7) * 4;

    // ---- prologue: issue K0 (buf0) + V0
    {
        const __nv_bfloat16* src = khalf ? KlB : KhB;
        cp16(pool + khalf * 2560 + kr * 80 + kcol * 2, src + (size_t)kr * NN + kcol);
    }
    #pragma unroll
    for (int j = 0; j < 4; j++) {
        int d = vd0 + j * 32;
        cp16(sV + d * VSTR + vch, VB + (size_t)d * NN + vch);
    }
    cp_commit();

    // ---- stage Q tiles transposed [q][kd] bf16 (hi -> P region, lo -> Kbuf1)
    #pragma unroll
    for (int i = 0; i < 4; i++) {
        int t = tid + i * 256;
        int kd = t >> 5, qp = t & 31;
        __nv_bfloat162 vh = *(const __nv_bfloat162*)&QhB[(size_t)kd * NN + n0 + 2 * qp];
        __nv_bfloat162 vl = *(const __nv_bfloat162*)&QlB[(size_t)kd * NN + n0 + 2 * qp];
        stQh[(2 * qp) * QSTRB + kd]     = vh.x;
        stQh[(2 * qp + 1) * QSTRB + kd] = vh.y;
        stQl[(2 * qp) * QSTRB + kd]     = vl.x;
        stQl[(2 * qp + 1) * QSTRB + kd] = vl.y;
    }
    if (tid < 64) sSum[tid] = 0.f;
    __syncthreads();

    // ---- hoist Q A-fragments via ldmatrix.x4 (m16k16, 2 k-steps)
    const int qbase = (w & 3) * 16;
    const int qrS   = qbase + lg;
    uint32_t ah[2][4], al[2][4];
    #pragma unroll
    for (int kt = 0; kt < 2; kt++) {
        int row = qbase + (lane & 15);
        int col = kt * 16 + (lane >> 4) * 8;
        ldm_x4(ah[kt], (uint32_t)__cvta_generic_to_shared(&stQh[row * QSTRB + col]));
        ldm_x4(al[kt], (uint32_t)__cvta_generic_to_shared(&stQl[row * QSTRB + col]));
    }
    __syncthreads();   // staging regions (P, Kbuf1) now free

    float Oc[8][4];
    #pragma unroll
    for (int nt = 0; nt < 8; nt++)
        #pragma unroll
        for (int j = 0; j < 4; j++) Oc[nt][j] = 0.f;

    float rsum0 = 0.f, rsum1 = 0.f;
    const int n0w = (w >> 2) * 16;
    const int d0w = w * 16;

    const int NTILE = NN / 32;           // 72
    for (int i = 0; i < NTILE; i++) {
        cp_wait<0>();
        __syncthreads();                              // [sync1]

        char* curK = pool + (i & 1) * 5120;
        char* nxtK = pool + ((i + 1) & 1) * 5120;

        // issue K(i+1)
        if (i + 1 < NTILE) {
            int m1 = (i + 1) * 32;
            const __nv_bfloat16* src = khalf ? KlB : KhB;
            cp16(nxtK + khalf * 2560 + kr * 80 + kcol * 2, src + (size_t)kr * NN + m1 + kcol);
        }

        // ---- S = Q K^T (bf16x2, 3 MMAs per (nt,kt)); warp: 16q x 16m
        __nv_bfloat16* cKh = (__nv_bfloat16*)curK;
        __nv_bfloat16* cKl = (__nv_bfloat16*)(curK + 2560);
        float sc[2][4];
        #pragma unroll
        for (int nt = 0; nt < 2; nt++) {
            sc[nt][0] = sc[nt][1] = sc[nt][2] = sc[nt][3] = 0.f;
            int mbase = n0w + nt * 8;
            #pragma unroll
            for (int kt = 0; kt < 2; kt++) {
                int brow = kt * 16 + (lane & 15);
                uint32_t bh0, bh1, bl0, bl1;
                ldm_x2t(bh0, bh1, (uint32_t)__cvta_generic_to_shared(&cKh[brow * KSTRB + mbase]));
                ldm_x2t(bl0, bl1, (uint32_t)__cvta_generic_to_shared(&cKl[brow * KSTRB + mbase]));
                mma_bf16(sc[nt], ah[kt], bh0, bh1);
                mma_bf16(sc[nt], al[kt], bh0, bh1);
                mma_bf16(sc[nt], ah[kt], bl0, bl1);
            }
        }

        // ---- hoist this warp's V_i fragments (own 16 d-rows)
        uint32_t va[4][4];
        #pragma unroll
        for (int kt = 0; kt < 4; kt++) {
            int kc = kt * 8 + lt;
            va[kt][0] = __float_as_uint(sV[(d0w + lg) * VSTR + kc]);
            va[kt][1] = __float_as_uint(sV[(d0w + 8 + lg) * VSTR + kc]);
            va[kt][2] = __float_as_uint(sV[(d0w + lg) * VSTR + kc + 4]);
            va[kt][3] = __float_as_uint(sV[(d0w + 8 + lg) * VSTR + kc + 4]);
        }

        // ---- P = rna(exp(S)); row sums from rounded values
        #pragma unroll
        for (int nt = 0; nt < 2; nt++) {
            float p0 = rn_tf32(fast_exp(sc[nt][0]));
            float p1 = rn_tf32(fast_exp(sc[nt][1]));
            float p2 = rn_tf32(fast_exp(sc[nt][2]));
            float p3 = rn_tf32(fast_exp(sc[nt][3]));
            rsum0 += p0 + p1;
            rsum1 += p2 + p3;
            int col = n0w + nt * 8 + 2 * lt;
            *(float2*)&sP[qrS * PSTR + col]       = make_float2(p0, p1);
            *(float2*)&sP[(qrS + 8) * PSTR + col] = make_float2(p2, p3);
        }
        __syncthreads();                              // [sync2]

        // issue V(i+1) (V_i hoisted by all warps)
        if (i + 1 < NTILE) {
            int m1 = (i + 1) * 32;
            #pragma unroll
            for (int j = 0; j < 4; j++) {
                int d = vd0 + j * 32;
                cp16(sV + d * VSTR + vch, VB + (size_t)d * NN + m1 + vch);
            }
        }
        cp_commit();

        // ---- O += V * P^T (tf32); warp: 16d x 64q
        #pragma unroll
        for (int kt = 0; kt < 4; kt++) {
            int kc = kt * 8 + lt;
            #pragma unroll
            for (int nt = 0; nt < 8; nt++) {
                uint32_t pb0 = __float_as_uint(sP[(nt * 8 + lg) * PSTR + kc]);
                uint32_t pb1 = __float_as_uint(sP[(nt * 8 + lg) * PSTR + kc + 4]);
                mma_tf32(Oc[nt], va[kt][0], va[kt][1], va[kt][2], va[kt][3], pb0, pb1);
            }
        }
    }

    // ---- fold row sums
    rsum0 += __shfl_xor_sync(0xffffffffu, rsum0, 1);
    rsum0 += __shfl_xor_sync(0xffffffffu, rsum0, 2);
    rsum1 += __shfl_xor_sync(0xffffffffu, rsum1, 1);
    rsum1 += __shfl_xor_sync(0xffffffffu, rsum1, 2);
    if (lt == 0) {
        atomicAdd(&sSum[qrS], rsum0);
        atomicAdd(&sSum[qrS + 8], rsum1);
    }
    __syncthreads();
    if (tid < 64) sSum[tid] = 1.0f / sSum[tid];
    __syncthreads();

    // ---- store relu(rna(o)) as [d][q], coalesced float2
    float* XXb = XX + ((size_t)b * DHCH + h * DDIM) * NN;
    #pragma unroll
    for (int nt = 0; nt < 8; nt++) {
        int qc = nt * 8 + 2 * lt;
        float i0 = sSum[qc], i1 = sSum[qc + 1];
        float o00 = rn_tf32(fmaxf(Oc[nt][0] * i0, 0.f));
        float o01 = rn_tf32(fmaxf(Oc[nt][1] * i1, 0.f));
        float o10 = rn_tf32(fmaxf(Oc[nt][2] * i0, 0.f));
        float o11 = rn_tf32(fmaxf(Oc[nt][3] * i1, 0.f));
        *(float2*)&XXb[(size_t)(d0w + lg) * NN + n0 + qc]     = make_float2(o00, o01);
        *(float2*)&XXb[(size_t)(d0w + 8 + lg) * NN + n0 + qc] = make_float2(o10, o11);
    }
}

// ---------------------------------------------------------------------------
extern "C" void kernel_launch(void* const* d_in, const int* in_sizes, int n_in,
                              void* d_out, int out_size)
{
    const float* x  = (const float*)d_in[0];
    const float* wq = (const float*)d_in[1];
    const float* gq = (const float*)d_in[2];
    const float* bq = (const float*)d_in[3];
    const float* wk = (const float*)d_in[4];
    const float* gk = (const float*)d_in[5];
    const float* bk = (const float*)d_in[6];
    const float* wv = (const float*)d_in[7];
    const float* gv = (const float*)d_in[8];
    const float* bv = (const float*)d_in[9];
    const float* wp = (const float*)d_in[10];
    const float* gp = (const float*)d_in[11];
    const float* bp = (const float*)d_in[12];
    float* out = (float*)d_out;

    __nv_bfloat16 *qh, *ql, *kh, *kl;
    float *v, *xx;
    float *wqh, *wql, *wkh, *wkl, *wvh, *wvl, *wph, *wpl;
    cudaGetSymbolAddress((void**)&qh,  g_qh);
    cudaGetSymbolAddress((void**)&ql,  g_ql);
    cudaGetSymbolAddress((void**)&kh,  g_kh);
    cudaGetSymbolAddress((void**)&kl,  g_kl);
    cudaGetSymbolAddress((void**)&v,   g_v);
    cudaGetSymbolAddress((void**)&xx,  g_xx);
    cudaGetSymbolAddress((void**)&wqh, g_wqh);
    cudaGetSymbolAddress((void**)&wql, g_wql);
    cudaGetSymbolAddress((void**)&wkh, g_wkh);
    cudaGetSymbolAddress((void**)&wkl, g_wkl);
    cudaGetSymbolAddress((void**)&wvh, g_wvh);
    cudaGetSymbolAddress((void**)&wvl, g_wvl);
    cudaGetSymbolAddress((void**)&wph, g_wph);
    cudaGetSymbolAddress((void**)&wpl, g_wpl);

    // 1) split weights
    prep_split_kernel<<<dim3(160, 4), 256>>>(wq, wk, wv, wp,
                                             wqh, wql, wkh, wkl,
                                             wvh, wvl, wph, wpl);

    // 2) fused Q/K/V projections
    proj_qkv_kernel<<<dim3(NN / 64, 24, BB), 256>>>(x,
        wqh, wql, gq, bq, wkh, wkl, gk, bk, wvh, wvl, gv, bv,
        qh, ql, kh, kl, v);

    // 3) fused attention
    attn_mma_kernel<<<dim3(NN / 64, NHEAD, BB), 256>>>(qh, ql, kh, kl, v, xx);

    // 4) output projection + BN
    proj_out_kernel<<<dim3(NN / 64, CCH / 64, BB), 256>>>(xx, wph, wpl, gp, bp, out);
}

// round 8
// speedup vs baseline: 3.7462x; 1.0790x over previous
#include <cuda_runtime.h>
#include <cuda_bf16.h>
#include <math_constants.h>
#include <cstdint>

#define EPSV 1e-5f

// Problem constants
#define NN    2304
#define NHEAD 8
#define KDIM  32
#define DDIM  128
#define CCH   256
#define DHCH  1024
#define BB    4

// Scratch (allocation-free rule: device globals)
__device__ __nv_bfloat16 g_xh[BB * CCH * NN],  g_xl[BB * CCH * NN];     // x bf16 pair
__device__ __nv_bfloat16 g_qh[BB * CCH * NN],  g_ql[BB * CCH * NN];     // Q bf16 pair
__device__ __nv_bfloat16 g_kh[BB * CCH * NN],  g_kl[BB * CCH * NN];     // K bf16 pair
__device__ float         g_v [BB * DHCH * NN];                          // tf32-rounded V
__device__ __nv_bfloat16 g_xxh[BB * DHCH * NN], g_xxl[BB * DHCH * NN];  // relu(attn) bf16 pair
__device__ __nv_bfloat16 g_wqh[CCH * CCH],  g_wql[CCH * CCH];
__device__ __nv_bfloat16 g_wkh[CCH * CCH],  g_wkl[CCH * CCH];
__device__ __nv_bfloat16 g_wvh[DHCH * CCH], g_wvl[DHCH * CCH];
__device__ __nv_bfloat16 g_wph[CCH * DHCH], g_wpl[CCH * DHCH];

// ---------------------------------------------------------------------------
// helpers
// ---------------------------------------------------------------------------
__device__ __forceinline__ uint32_t f2tf32(float x) {
    uint32_t r;
    asm("cvt.rna.tf32.f32 %0, %1;" : "=r"(r) : "f"(x));
    return r;
}
__device__ __forceinline__ float rn_tf32(float x) {
    return __uint_as_float(f2tf32(x));
}

__device__ __forceinline__ void mma_tf32(float c[4], uint32_t a0, uint32_t a1,
                                         uint32_t a2, uint32_t a3,
                                         uint32_t b0, uint32_t b1) {
    asm volatile(
        "mma.sync.aligned.m16n8k8.row.col.f32.tf32.tf32.f32 "
        "{%0,%1,%2,%3}, {%4,%5,%6,%7}, {%8,%9}, {%0,%1,%2,%3};\n"
        : "+f"(c[0]), "+f"(c[1]), "+f"(c[2]), "+f"(c[3])
        : "r"(a0), "r"(a1), "r"(a2), "r"(a3), "r"(b0), "r"(b1));
}

__device__ __forceinline__ void mma_bf16(float c[4], const uint32_t a[4],
                                         uint32_t b0, uint32_t b1) {
    asm volatile(
        "mma.sync.aligned.m16n8k16.row.col.f32.bf16.bf16.f32 "
        "{%0,%1,%2,%3}, {%4,%5,%6,%7}, {%8,%9}, {%0,%1,%2,%3};\n"
        : "+f"(c[0]), "+f"(c[1]), "+f"(c[2]), "+f"(c[3])
        : "r"(a[0]), "r"(a[1]), "r"(a[2]), "r"(a[3]), "r"(b0), "r"(b1));
}

__device__ __forceinline__ void ldm_x4(uint32_t r[4], uint32_t addr) {
    asm volatile("ldmatrix.sync.aligned.m8n8.x4.shared.b16 {%0,%1,%2,%3}, [%4];"
        : "=r"(r[0]), "=r"(r[1]), "=r"(r[2]), "=r"(r[3]) : "r"(addr));
}
__device__ __forceinline__ void ldm_x2t(uint32_t& r0, uint32_t& r1, uint32_t addr) {
    asm volatile("ldmatrix.sync.aligned.m8n8.x2.trans.shared.b16 {%0,%1}, [%2];"
        : "=r"(r0), "=r"(r1) : "r"(addr));
}

__device__ __forceinline__ void cp16(void* sdst, const void* gsrc) {
    uint32_t s = (uint32_t)__cvta_generic_to_shared(sdst);
    asm volatile("cp.async.ca.shared.global [%0], [%1], 16;" :: "r"(s), "l"(gsrc));
}
__device__ __forceinline__ void cp_commit() {
    asm volatile("cp.async.commit_group;");
}
template <int N>
__device__ __forceinline__ void cp_wait() {
    asm volatile("cp.async.wait_group %0;" :: "n"(N));
}

// exp on the FMA pipe (no MUFU). |rel err| ~2e-6 for |x| < 30.
__device__ __forceinline__ float fast_exp(float x) {
    float t = x * 1.4426950408889634f;
    float r = rintf(t);
    float f = t - r;
    float p = 0.0013333558f;
    p = fmaf(p, f, 0.0096181291f);
    p = fmaf(p, f, 0.0555041086f);
    p = fmaf(p, f, 0.2402265069f);
    p = fmaf(p, f, 0.6931471806f);
    p = fmaf(p, f, 1.0f);
    int e = (__float2int_rn(r) + 127) << 23;
    return p * __int_as_float(e);
}

// ---------------------------------------------------------------------------
// Prep: split weights + x into bf16 hi/lo pairs. blockIdx.y = task.
// ---------------------------------------------------------------------------
__global__ void prep_split_kernel(const float* __restrict__ wq, const float* __restrict__ wk,
                                  const float* __restrict__ wv, const float* __restrict__ wp,
                                  const float* __restrict__ x,
                                  __nv_bfloat16* __restrict__ wqh, __nv_bfloat16* __restrict__ wql,
                                  __nv_bfloat16* __restrict__ wkh, __nv_bfloat16* __restrict__ wkl,
                                  __nv_bfloat16* __restrict__ wvh, __nv_bfloat16* __restrict__ wvl,
                                  __nv_bfloat16* __restrict__ wph, __nv_bfloat16* __restrict__ wpl,
                                  __nv_bfloat16* __restrict__ xh,  __nv_bfloat16* __restrict__ xl)
{
    const float* src; __nv_bfloat16* h; __nv_bfloat16* l; int n;
    switch (blockIdx.y) {
        case 0:  src = wq; h = wqh; l = wql; n = CCH * CCH;    break;
        case 1:  src = wk; h = wkh; l = wkl; n = CCH * CCH;    break;
        case 2:  src = wv; h = wvh; l = wvl; n = DHCH * CCH;   break;
        case 3:  src = wp; h = wph; l = wpl; n = CCH * DHCH;   break;
        default: src = x;  h = xh;  l = xl;  n = BB * CCH * NN; break;
    }
    for (int i = blockIdx.x * blockDim.x + threadIdx.x; i < n; i += gridDim.x * blockDim.x) {
        float v = src[i];
        __nv_bfloat16 hv = __float2bfloat16_rn(v);
        h[i] = hv;
        l[i] = __float2bfloat16_rn(v - __bfloat162float(hv));
    }
}

// ---------------------------------------------------------------------------
// bf16-pair 3-MMA projection + BN.
//   Y = sum_c (Wh+Wl)(Xh+Xl), keeping whxh + wlxh + whxl.
// Tiles 64o x 64n, k-chunks of 16, cp.async double buffered, ldmatrix feeds.
// mode 0: fp32 store. mode 1: bf16 pair store. mode 2: tf32-rounded fp32 store.
// smem (bf16): sW[2buf][2half][64*24]  sX[2buf][2half][16*72]
// ---------------------------------------------------------------------------
#define PWSTR 24
#define PXSTR 72
__device__ __forceinline__ void proj_body(
    const __nv_bfloat16* __restrict__ Xh, const __nv_bfloat16* __restrict__ Xl,  // [C][NN]
    const __nv_bfloat16* __restrict__ Wh, const __nv_bfloat16* __restrict__ Wl,  // [O][C]
    const float* __restrict__ gbn, const float* __restrict__ bbn,
    float* __restrict__ Y0, __nv_bfloat16* __restrict__ Yh, __nv_bfloat16* __restrict__ Yl,
    int C, int O, int mode, int b, int o0, int n0,
    __nv_bfloat16* sW, __nv_bfloat16* sX)
{
    const int tid = threadIdx.x;
    const int lane = tid & 31;
    const int w  = tid >> 5;
    const int lg = lane >> 2;
    const int lt = lane & 3;
    const int ow = (w & 3) * 16;
    const int nw = (w >> 2) * 32;

    // loader maps (each thread: one 16B W chunk + one 16B X chunk per stage)
    const int lhalf = tid >> 7;          // 0 = hi, 1 = lo
    const int li    = tid & 127;
    const int wrow  = li >> 1, wchk = (li & 1) * 8;
    const int xrow  = li >> 3, xchk = (li & 7) * 8;
    const __nv_bfloat16* Wsrc = lhalf ? Wl : Wh;
    const __nv_bfloat16* Xsrc = lhalf ? Xl : Xh;

    const int steps = C / 16;
    #define SW(buf, half) (sW + ((buf) * 2 + (half)) * 64 * PWSTR)
    #define SX(buf, half) (sX + ((buf) * 2 + (half)) * 16 * PXSTR)

    cp16(SW(0, lhalf) + wrow * PWSTR + wchk, Wsrc + (size_t)(o0 + wrow) * C + wchk);
    cp16(SX(0, lhalf) + xrow * PXSTR + xchk, Xsrc + (size_t)xrow * NN + n0 + xchk);
    cp_commit();

    float Oc[4][4];
    #pragma unroll
    for (int nt = 0; nt < 4; nt++)
        #pragma unroll
        for (int j = 0; j < 4; j++) Oc[nt][j] = 0.f;

    for (int s = 0; s < steps; s++) {
        const int cur = s & 1, nxt = cur ^ 1;
        if (s + 1 < steps) {
            int c0 = (s + 1) * 16;
            cp16(SW(nxt, lhalf) + wrow * PWSTR + wchk, Wsrc + (size_t)(o0 + wrow) * C + c0 + wchk);
            cp16(SX(nxt, lhalf) + xrow * PXSTR + xchk, Xsrc + (size_t)(c0 + xrow) * NN + n0 + xchk);
        }
        cp_commit();
        cp_wait<1>();
        __syncthreads();

        // A fragments (W, 16o x 16c) via ldmatrix.x4
        uint32_t ahf[4], alf[4];
        {
            int row = ow + (lane & 15);
            int col = (lane >> 4) * 8;
            ldm_x4(ahf, (uint32_t)__cvta_generic_to_shared(SW(cur, 0) + row * PWSTR + col));
            ldm_x4(alf, (uint32_t)__cvta_generic_to_shared(SW(cur, 1) + row * PWSTR + col));
        }
        #pragma unroll
        for (int nt = 0; nt < 4; nt++) {
            int nbase = nw + nt * 8;
            uint32_t bh0, bh1, bl0, bl1;
            ldm_x2t(bh0, bh1, (uint32_t)__cvta_generic_to_shared(SX(cur, 0) + (lane & 15) * PXSTR + nbase));
            ldm_x2t(bl0, bl1, (uint32_t)__cvta_generic_to_shared(SX(cur, 1) + (lane & 15) * PXSTR + nbase));
            mma_bf16(Oc[nt], ahf, bh0, bh1);
            mma_bf16(Oc[nt], alf, bh0, bh1);
            mma_bf16(Oc[nt], ahf, bl0, bl1);
        }
        __syncthreads();
    }
    #undef SW
    #undef SX

    const float rs = rsqrtf(1.f + EPSV);
    const int oa = o0 + ow + lg;
    const int ob = oa + 8;
    const float sa = gbn[oa] * rs, ba = bbn[oa];
    const float sb = gbn[ob] * rs, bb2 = bbn[ob];

    #pragma unroll
    for (int nt = 0; nt < 4; nt++) {
        int n = n0 + nw + nt * 8 + 2 * lt;
        float ya0 = Oc[nt][0] * sa + ba;
        float ya1 = Oc[nt][1] * sa + ba;
        float yb0 = Oc[nt][2] * sb + bb2;
        float yb1 = Oc[nt][3] * sb + bb2;
        size_t ia = ((size_t)b * O + oa) * NN + n;
        size_t ib = ((size_t)b * O + ob) * NN + n;
        if (mode == 0) {
            *(float2*)&Y0[ia] = make_float2(ya0, ya1);
            *(float2*)&Y0[ib] = make_float2(yb0, yb1);
        } else if (mode == 1) {
            __nv_bfloat162 ha, hb, la, lb;
            ha.x = __float2bfloat16_rn(ya0);
            ha.y = __float2bfloat16_rn(ya1);
            hb.x = __float2bfloat16_rn(yb0);
            hb.y = __float2bfloat16_rn(yb1);
            la.x = __float2bfloat16_rn(ya0 - __bfloat162float(ha.x));
            la.y = __float2bfloat16_rn(ya1 - __bfloat162float(ha.y));
            lb.x = __float2bfloat16_rn(yb0 - __bfloat162float(hb.x));
            lb.y = __float2bfloat16_rn(yb1 - __bfloat162float(hb.y));
            *(__nv_bfloat162*)&Yh[ia] = ha;
            *(__nv_bfloat162*)&Yh[ib] = hb;
            *(__nv_bfloat162*)&Yl[ia] = la;
            *(__nv_bfloat162*)&Yl[ib] = lb;
        } else {
            *(float2*)&Y0[ia] = make_float2(rn_tf32(ya0), rn_tf32(ya1));
            *(float2*)&Y0[ib] = make_float2(rn_tf32(yb0), rn_tf32(yb1));
        }
    }
}

// Fused Q/K/V projection: blockIdx.y segments (0-3 Q, 4-7 K, 8-23 V)
__global__ __launch_bounds__(256, 2)
void proj_qkv_kernel(const __nv_bfloat16* __restrict__ xh, const __nv_bfloat16* __restrict__ xl,
                     const __nv_bfloat16* __restrict__ wqh, const __nv_bfloat16* __restrict__ wql,
                     const float* __restrict__ gq,  const float* __restrict__ bq,
                     const __nv_bfloat16* __restrict__ wkh, const __nv_bfloat16* __restrict__ wkl,
                     const float* __restrict__ gk,  const float* __restrict__ bk,
                     const __nv_bfloat16* __restrict__ wvh, const __nv_bfloat16* __restrict__ wvl,
                     const float* __restrict__ gv,  const float* __restrict__ bv,
                     __nv_bfloat16* __restrict__ qh, __nv_bfloat16* __restrict__ ql,
                     __nv_bfloat16* __restrict__ kh, __nv_bfloat16* __restrict__ kl,
                     float* __restrict__ v)
{
    __shared__ __align__(16) __nv_bfloat16 sW[2 * 2 * 64 * PWSTR];
    __shared__ __align__(16) __nv_bfloat16 sX[2 * 2 * 16 * PXSTR];

    const int seg = blockIdx.y;
    const int b   = blockIdx.z;
    const int n0  = blockIdx.x * 64;

    const __nv_bfloat16* Wh; const __nv_bfloat16* Wl; const float* g; const float* be;
    float* Y0 = nullptr; __nv_bfloat16* Yh = nullptr; __nv_bfloat16* Yl = nullptr;
    int O, mode, o0;
    if (seg < 4)      { Wh = wqh; Wl = wql; g = gq; be = bq; Yh = qh; Yl = ql; O = CCH;  mode = 1; o0 = seg * 64; }
    else if (seg < 8) { Wh = wkh; Wl = wkl; g = gk; be = bk; Yh = kh; Yl = kl; O = CCH;  mode = 1; o0 = (seg - 4) * 64; }
    else              { Wh = wvh; Wl = wvl; g = gv; be = bv; Y0 = v;  O = DHCH; mode = 2; o0 = (seg - 8) * 64; }

    proj_body(xh + (size_t)b * CCH * NN, xl + (size_t)b * CCH * NN,
              Wh, Wl, g, be, Y0, Yh, Yl, CCH, O, mode, b, o0, n0, sW, sX);
}

// Final projection (C=1024, input = xx bf16 pair from attn)
__global__ __launch_bounds__(256, 2)
void proj_out_kernel(const __nv_bfloat16* __restrict__ xxh, const __nv_bfloat16* __restrict__ xxl,
                     const __nv_bfloat16* __restrict__ wph, const __nv_bfloat16* __restrict__ wpl,
                     const float* __restrict__ gp,  const float* __restrict__ bp,
                     float* __restrict__ out)
{
    __shared__ __align__(16) __nv_bfloat16 sW[2 * 2 * 64 * PWSTR];
    __shared__ __align__(16) __nv_bfloat16 sX[2 * 2 * 16 * PXSTR];

    const int b  = blockIdx.z;
    const int o0 = blockIdx.y * 64;
    const int n0 = blockIdx.x * 64;

    proj_body(xxh + (size_t)b * DHCH * NN, xxl + (size_t)b * DHCH * NN,
              wph, wpl, gp, bp, out, nullptr, nullptr,
              DHCH, CCH, /*mode=*/0, b, o0, n0, sW, sX);
}

// ---------------------------------------------------------------------------
// Tensor-core fused attention (R7 mainloop, epilogue emits bf16 pair).
// ---------------------------------------------------------------------------
#define KSTRB 40
#define QSTRB 40
#define VSTR 36
#define PSTR 36
#define POOL_BYTES 38144

__global__ __launch_bounds__(256, 2)
void attn_mma_kernel(const __nv_bfloat16* __restrict__ Qh, const __nv_bfloat16* __restrict__ Ql,
                     const __nv_bfloat16* __restrict__ Kh, const __nv_bfloat16* __restrict__ Kl,
                     const float* __restrict__ V,
                     __nv_bfloat16* __restrict__ XXh, __nv_bfloat16* __restrict__ XXl)
{
    __shared__ __align__(16) char pool[POOL_BYTES];
    float* sV   = (float*)(pool + 10240);
    float* sP   = (float*)(pool + 28672);
    float* sSum = (float*)(pool + 37888);
    __nv_bfloat16* stQh = (__nv_bfloat16*)(pool + 28672);
    __nv_bfloat16* stQl = (__nv_bfloat16*)(pool + 5120);

    const int tid  = threadIdx.x;
    const int lane = tid & 31;
    const int w    = tid >> 5;
    const int lg   = lane >> 2;
    const int lt   = lane & 3;

    const int n0 = blockIdx.x * 64;
    const int h  = blockIdx.y;
    const int b  = blockIdx.z;

    const __nv_bfloat16* QhB = Qh + ((size_t)b * CCH + h * KDIM) * NN;
    const __nv_bfloat16* QlB = Ql + ((size_t)b * CCH + h * KDIM) * NN;
    const __nv_bfloat16* KhB = Kh + ((size_t)b * CCH + h * KDIM) * NN;
    const __nv_bfloat16* KlB = Kl + ((size_t)b * CCH + h * KDIM) * NN;
    const float* VB = V + ((size_t)b * DHCH + h * DDIM) * NN;

    const int khalf = tid >> 7;
    const int kr    = (tid & 127) >> 2;
    const int kcol  = (tid & 3) * 8;
    const int vd0 = tid >> 3;
    const int vch = (tid & 7) * 4;

    // ---- prologue: issue K0 (buf0) + V0
    {
        const __nv_bfloat16* src = khalf ? KlB : KhB;
        cp16(pool + khalf * 2560 + kr * 80 + kcol * 2, src + (size_t)kr * NN + kcol);
    }
    #pragma unroll
    for (int j = 0; j < 4; j++) {
        int d = vd0 + j * 32;
        cp16(sV + d * VSTR + vch, VB + (size_t)d * NN + vch);
    }
    cp_commit();

    // ---- stage Q tiles transposed [q][kd] bf16
    #pragma unroll
    for (int i = 0; i < 4; i++) {
        int t = tid + i * 256;
        int kd = t >> 5, qp = t & 31;
        __nv_bfloat162 vh = *(const __nv_bfloat162*)&QhB[(size_t)kd * NN + n0 + 2 * qp];
        __nv_bfloat162 vl = *(const __nv_bfloat162*)&QlB[(size_t)kd * NN + n0 + 2 * qp];
        stQh[(2 * qp) * QSTRB + kd]     = vh.x;
        stQh[(2 * qp + 1) * QSTRB + kd] = vh.y;
        stQl[(2 * qp) * QSTRB + kd]     = vl.x;
        stQl[(2 * qp + 1) * QSTRB + kd] = vl.y;
    }
    if (tid < 64) sSum[tid] = 0.f;
    __syncthreads();

    // ---- hoist Q A-fragments via ldmatrix.x4
    const int qbase = (w & 3) * 16;
    const int qrS   = qbase + lg;
    uint32_t ah[2][4], al[2][4];
    #pragma unroll
    for (int kt = 0; kt < 2; kt++) {
        int row = qbase + (lane & 15);
        int col = kt * 16 + (lane >> 4) * 8;
        ldm_x4(ah[kt], (uint32_t)__cvta_generic_to_shared(&stQh[row * QSTRB + col]));
        ldm_x4(al[kt], (uint32_t)__cvta_generic_to_shared(&stQl[row * QSTRB + col]));
    }
    __syncthreads();

    float Oc[8][4];
    #pragma unroll
    for (int nt = 0; nt < 8; nt++)
        #pragma unroll
        for (int j = 0; j < 4; j++) Oc[nt][j] = 0.f;

    float rsum0 = 0.f, rsum1 = 0.f;
    const int n0w = (w >> 2) * 16;
    const int d0w = w * 16;

    const int NTILE = NN / 32;
    for (int i = 0; i < NTILE; i++) {
        cp_wait<0>();
        __syncthreads();

        char* curK = pool + (i & 1) * 5120;
        char* nxtK = pool + ((i + 1) & 1) * 5120;

        if (i + 1 < NTILE) {
            int m1 = (i + 1) * 32;
            const __nv_bfloat16* src = khalf ? KlB : KhB;
            cp16(nxtK + khalf * 2560 + kr * 80 + kcol * 2, src + (size_t)kr * NN + m1 + kcol);
        }

        __nv_bfloat16* cKh = (__nv_bfloat16*)curK;
        __nv_bfloat16* cKl = (__nv_bfloat16*)(curK + 2560);
        float sc[2][4];
        #pragma unroll
        for (int nt = 0; nt < 2; nt++) {
            sc[nt][0] = sc[nt][1] = sc[nt][2] = sc[nt][3] = 0.f;
            int mbase = n0w + nt * 8;
            #pragma unroll
            for (int kt = 0; kt < 2; kt++) {
                int brow = kt * 16 + (lane & 15);
                uint32_t bh0, bh1, bl0, bl1;
                ldm_x2t(bh0, bh1, (uint32_t)__cvta_generic_to_shared(&cKh[brow * KSTRB + mbase]));
                ldm_x2t(bl0, bl1, (uint32_t)__cvta_generic_to_shared(&cKl[brow * KSTRB + mbase]));
                mma_bf16(sc[nt], ah[kt], bh0, bh1);
                mma_bf16(sc[nt], al[kt], bh0, bh1);
                mma_bf16(sc[nt], ah[kt], bl0, bl1);
            }
        }

        uint32_t va[4][4];
        #pragma unroll
        for (int kt = 0; kt < 4; kt++) {
            int kc = kt * 8 + lt;
            va[kt][0] = __float_as_uint(sV[(d0w + lg) * VSTR + kc]);
            va[kt][1] = __float_as_uint(sV[(d0w + 8 + lg) * VSTR + kc]);
            va[kt][2] = __float_as_uint(sV[(d0w + lg) * VSTR + kc + 4]);
            va[kt][3] = __float_as_uint(sV[(d0w + 8 + lg) * VSTR + kc + 4]);
        }

        #pragma unroll
        for (int nt = 0; nt < 2; nt++) {
            float p0 = rn_tf32(fast_exp(sc[nt][0]));
            float p1 = rn_tf32(fast_exp(sc[nt][1]));
            float p2 = rn_tf32(fast_exp(sc[nt][2]));
            float p3 = rn_tf32(fast_exp(sc[nt][3]));
            rsum0 += p0 + p1;
            rsum1 += p2 + p3;
            int col = n0w + nt * 8 + 2 * lt;
            *(float2*)&sP[qrS * PSTR + col]       = make_float2(p0, p1);
            *(float2*)&sP[(qrS + 8) * PSTR + col] = make_float2(p2, p3);
        }
        __syncthreads();

        if (i + 1 < NTILE) {
            int m1 = (i + 1) * 32;
            #pragma unroll
            for (int j = 0; j < 4; j++) {
                int d = vd0 + j * 32;
                cp16(sV + d * VSTR + vch, VB + (size_t)d * NN + m1 + vch);
            }
        }
        cp_commit();

        #pragma unroll
        for (int kt = 0; kt < 4; kt++) {
            int kc = kt * 8 + lt;
            #pragma unroll
            for (int nt = 0; nt < 8; nt++) {
                uint32_t pb0 = __float_as_uint(sP[(nt * 8 + lg) * PSTR + kc]);
                uint32_t pb1 = __float_as_uint(sP[(nt * 8 + lg) * PSTR + kc + 4]);
                mma_tf32(Oc[nt], va[kt][0], va[kt][1], va[kt][2], va[kt][3], pb0, pb1);
            }
        }
    }

    // ---- fold row sums
    rsum0 += __shfl_xor_sync(0xffffffffu, rsum0, 1);
    rsum0 += __shfl_xor_sync(0xffffffffu, rsum0, 2);
    rsum1 += __shfl_xor_sync(0xffffffffu, rsum1, 1);
    rsum1 += __shfl_xor_sync(0xffffffffu, rsum1, 2);
    if (lt == 0) {
        atomicAdd(&sSum[qrS], rsum0);
        atomicAdd(&sSum[qrS + 8], rsum1);
    }
    __syncthreads();
    if (tid < 64) sSum[tid] = 1.0f / sSum[tid];
    __syncthreads();

    // ---- store relu(o) as bf16 hi/lo pair, [d][q]
    __nv_bfloat16* XhB = XXh + ((size_t)b * DHCH + h * DDIM) * NN;
    __nv_bfloat16* XlB = XXl + ((size_t)b * DHCH + h * DDIM) * NN;
    #pragma unroll
    for (int nt = 0; nt < 8; nt++) {
        int qc = nt * 8 + 2 * lt;
        float i0 = sSum[qc], i1 = sSum[qc + 1];
        float o00 = fmaxf(Oc[nt][0] * i0, 0.f);
        float o01 = fmaxf(Oc[nt][1] * i1, 0.f);
        float o10 = fmaxf(Oc[nt][2] * i0, 0.f);
        float o11 = fmaxf(Oc[nt][3] * i1, 0.f);
        __nv_bfloat162 h0, l0, h1, l1;
        h0.x = __float2bfloat16_rn(o00);
        h0.y = __float2bfloat16_rn(o01);
        h1.x = __float2bfloat16_rn(o10);
        h1.y = __float2bfloat16_rn(o11);
        l0.x = __float2bfloat16_rn(o00 - __bfloat162float(h0.x));
        l0.y = __float2bfloat16_rn(o01 - __bfloat162float(h0.y));
        l1.x = __float2bfloat16_rn(o10 - __bfloat162float(h1.x));
        l1.y = __float2bfloat16_rn(o11 - __bfloat162float(h1.y));
        size_t ia = (size_t)(d0w + lg) * NN + n0 + qc;
        size_t ib = (size_t)(d0w + 8 + lg) * NN + n0 + qc;
        *(__nv_bfloat162*)&XhB[ia] = h0;
        *(__nv_bfloat162*)&XlB[ia] = l0;
        *(__nv_bfloat162*)&XhB[ib] = h1;
        *(__nv_bfloat162*)&XlB[ib] = l1;
    }
}

// ---------------------------------------------------------------------------
extern "C" void kernel_launch(void* const* d_in, const int* in_sizes, int n_in,
                              void* d_out, int out_size)
{
    const float* x  = (const float*)d_in[0];
    const float* wq = (const float*)d_in[1];
    const float* gq = (const float*)d_in[2];
    const float* bq = (const float*)d_in[3];
    const float* wk = (const float*)d_in[4];
    const float* gk = (const float*)d_in[5];
    const float* bk = (const float*)d_in[6];
    const float* wv = (const float*)d_in[7];
    const float* gv = (const float*)d_in[8];
    const float* bv = (const float*)d_in[9];
    const float* wp = (const float*)d_in[10];
    const float* gp = (const float*)d_in[11];
    const float* bp = (const float*)d_in[12];
    float* out = (float*)d_out;

    __nv_bfloat16 *xh, *xl, *qh, *ql, *kh, *kl, *xxh, *xxl;
    __nv_bfloat16 *wqh, *wql, *wkh, *wkl, *wvh, *wvl, *wph, *wpl;
    float *v;
    cudaGetSymbolAddress((void**)&xh,  g_xh);
    cudaGetSymbolAddress((void**)&xl,  g_xl);
    cudaGetSymbolAddress((void**)&qh,  g_qh);
    cudaGetSymbolAddress((void**)&ql,  g_ql);
    cudaGetSymbolAddress((void**)&kh,  g_kh);
    cudaGetSymbolAddress((void**)&kl,  g_kl);
    cudaGetSymbolAddress((void**)&v,   g_v);
    cudaGetSymbolAddress((void**)&xxh, g_xxh);
    cudaGetSymbolAddress((void**)&xxl, g_xxl);
    cudaGetSymbolAddress((void**)&wqh, g_wqh);
    cudaGetSymbolAddress((void**)&wql, g_wql);
    cudaGetSymbolAddress((void**)&wkh, g_wkh);
    cudaGetSymbolAddress((void**)&wkl, g_wkl);
    cudaGetSymbolAddress((void**)&wvh, g_wvh);
    cudaGetSymbolAddress((void**)&wvl, g_wvl);
    cudaGetSymbolAddress((void**)&wph, g_wph);
    cudaGetSymbolAddress((void**)&wpl, g_wpl);

    // 1) split weights + x to bf16 pairs
    prep_split_kernel<<<dim3(256, 5), 256>>>(wq, wk, wv, wp, x,
                                             wqh, wql, wkh, wkl,
                                             wvh, wvl, wph, wpl, xh, xl);

    // 2) fused Q/K/V projections (bf16 3-MMA)
    proj_qkv_kernel<<<dim3(NN / 64, 24, BB), 256>>>(xh, xl,
        wqh, wql, gq, bq, wkh, wkl, gk, bk, wvh, wvl, gv, bv,
        qh, ql, kh, kl, v);

    // 3) fused attention
    attn_mma_kernel<<<dim3(NN / 64, NHEAD, BB), 256>>>(qh, ql, kh, kl, v, xxh, xxl);

    // 4) output projection + BN (bf16 3-MMA)
    proj_out_kernel<<<dim3(NN / 64, CCH / 64, BB), 256>>>(xxh, xxl, wph, wpl, gp, bp, out);
}

// round 9
// speedup vs baseline: 5.0308x; 1.3429x over previous
#include <cuda_runtime.h>
#include <cuda_bf16.h>
#include <cuda_fp16.h>
#include <math_constants.h>
#include <cstdint>

#define EPSV 1e-5f

// Problem constants
#define NN    2304
#define NHEAD 8
#define KDIM  32
#define DDIM  128
#define CCH   256
#define DHCH  1024
#define BB    4

#define SSHIFT 16.0f   // softmax shift: P' = exp(S - 16), keeps P' in fp16 range

// Scratch (allocation-free rule: device globals)
__device__ __nv_bfloat16 g_xh[BB * CCH * NN],  g_xl[BB * CCH * NN];     // x bf16 pair
__device__ __half        g_qh[BB * CCH * NN],  g_ql[BB * CCH * NN];     // Q fp16 pair
__device__ __half        g_kh[BB * CCH * NN],  g_kl[BB * CCH * NN];     // K fp16 pair
__device__ __half        g_v [BB * DHCH * NN];                          // V fp16
__device__ __nv_bfloat16 g_xxh[BB * DHCH * NN], g_xxl[BB * DHCH * NN];  // relu(attn) bf16 pair
__device__ __nv_bfloat16 g_wqh[CCH * CCH],  g_wql[CCH * CCH];
__device__ __nv_bfloat16 g_wkh[CCH * CCH],  g_wkl[CCH * CCH];
__device__ __nv_bfloat16 g_wvh[DHCH * CCH], g_wvl[DHCH * CCH];
__device__ __nv_bfloat16 g_wph[CCH * DHCH], g_wpl[CCH * DHCH];

// ---------------------------------------------------------------------------
// helpers
// ---------------------------------------------------------------------------
__device__ __forceinline__ void mma_bf16(float c[4], const uint32_t a[4],
                                         uint32_t b0, uint32_t b1) {
    asm volatile(
        "mma.sync.aligned.m16n8k16.row.col.f32.bf16.bf16.f32 "
        "{%0,%1,%2,%3}, {%4,%5,%6,%7}, {%8,%9}, {%0,%1,%2,%3};\n"
        : "+f"(c[0]), "+f"(c[1]), "+f"(c[2]), "+f"(c[3])
        : "r"(a[0]), "r"(a[1]), "r"(a[2]), "r"(a[3]), "r"(b0), "r"(b1));
}
__device__ __forceinline__ void mma_f16(float c[4], const uint32_t a[4],
                                        uint32_t b0, uint32_t b1) {
    asm volatile(
        "mma.sync.aligned.m16n8k16.row.col.f32.f16.f16.f32 "
        "{%0,%1,%2,%3}, {%4,%5,%6,%7}, {%8,%9}, {%0,%1,%2,%3};\n"
        : "+f"(c[0]), "+f"(c[1]), "+f"(c[2]), "+f"(c[3])
        : "r"(a[0]), "r"(a[1]), "r"(a[2]), "r"(a[3]), "r"(b0), "r"(b1));
}

__device__ __forceinline__ void ldm_x4(uint32_t r[4], uint32_t addr) {
    asm volatile("ldmatrix.sync.aligned.m8n8.x4.shared.b16 {%0,%1,%2,%3}, [%4];"
        : "=r"(r[0]), "=r"(r[1]), "=r"(r[2]), "=r"(r[3]) : "r"(addr));
}
__device__ __forceinline__ void ldm_x4t(uint32_t r[4], uint32_t addr) {
    asm volatile("ldmatrix.sync.aligned.m8n8.x4.trans.shared.b16 {%0,%1,%2,%3}, [%4];"
        : "=r"(r[0]), "=r"(r[1]), "=r"(r[2]), "=r"(r[3]) : "r"(addr));
}
__device__ __forceinline__ void ldm_x2t(uint32_t& r0, uint32_t& r1, uint32_t addr) {
    asm volatile("ldmatrix.sync.aligned.m8n8.x2.trans.shared.b16 {%0,%1}, [%2];"
        : "=r"(r0), "=r"(r1) : "r"(addr));
}

__device__ __forceinline__ void cp16(void* sdst, const void* gsrc) {
    uint32_t s = (uint32_t)__cvta_generic_to_shared(sdst);
    asm volatile("cp.async.ca.shared.global [%0], [%1], 16;" :: "r"(s), "l"(gsrc));
}
__device__ __forceinline__ void cp_commit() {
    asm volatile("cp.async.commit_group;");
}
template <int N>
__device__ __forceinline__ void cp_wait() {
    asm volatile("cp.async.wait_group %0;" :: "n"(N));
}

// exp on the FMA pipe. |rel err| ~2e-6, valid for x in (-85, 30).
__device__ __forceinline__ float fast_exp(float x) {
    float t = x * 1.4426950408889634f;
    float r = rintf(t);
    float f = t - r;
    float p = 0.0013333558f;
    p = fmaf(p, f, 0.0096181291f);
    p = fmaf(p, f, 0.0555041086f);
    p = fmaf(p, f, 0.2402265069f);
    p = fmaf(p, f, 0.6931471806f);
    p = fmaf(p, f, 1.0f);
    int e = (__float2int_rn(r) + 127) << 23;
    return p * __int_as_float(e);
}

// ---------------------------------------------------------------------------
// Prep: split weights + x into bf16 hi/lo pairs. blockIdx.y = task.
// ---------------------------------------------------------------------------
__global__ void prep_split_kernel(const float* __restrict__ wq, const float* __restrict__ wk,
                                  const float* __restrict__ wv, const float* __restrict__ wp,
                                  const float* __restrict__ x,
                                  __nv_bfloat16* __restrict__ wqh, __nv_bfloat16* __restrict__ wql,
                                  __nv_bfloat16* __restrict__ wkh, __nv_bfloat16* __restrict__ wkl,
                                  __nv_bfloat16* __restrict__ wvh, __nv_bfloat16* __restrict__ wvl,
                                  __nv_bfloat16* __restrict__ wph, __nv_bfloat16* __restrict__ wpl,
                                  __nv_bfloat16* __restrict__ xh,  __nv_bfloat16* __restrict__ xl)
{
    const float* src; __nv_bfloat16* h; __nv_bfloat16* l; int n;
    switch (blockIdx.y) {
        case 0:  src = wq; h = wqh; l = wql; n = CCH * CCH;    break;
        case 1:  src = wk; h = wkh; l = wkl; n = CCH * CCH;    break;
        case 2:  src = wv; h = wvh; l = wvl; n = DHCH * CCH;   break;
        case 3:  src = wp; h = wph; l = wpl; n = CCH * DHCH;   break;
        default: src = x;  h = xh;  l = xl;  n = BB * CCH * NN; break;
    }
    for (int i = blockIdx.x * blockDim.x + threadIdx.x; i < n; i += gridDim.x * blockDim.x) {
        float v = src[i];
        __nv_bfloat16 hv = __float2bfloat16_rn(v);
        h[i] = hv;
        l[i] = __float2bfloat16_rn(v - __bfloat162float(hv));
    }
}

// ---------------------------------------------------------------------------
// bf16-pair 3-MMA projection + BN.
// mode 0: fp32 store. mode 1: fp16 pair store (Q/K). mode 2: fp16 store (V).
// ---------------------------------------------------------------------------
#define PWSTR 24
#define PXSTR 72
__device__ __forceinline__ void proj_body(
    const __nv_bfloat16* __restrict__ Xh, const __nv_bfloat16* __restrict__ Xl,
    const __nv_bfloat16* __restrict__ Wh, const __nv_bfloat16* __restrict__ Wl,
    const float* __restrict__ gbn, const float* __restrict__ bbn,
    float* __restrict__ Y0, __half* __restrict__ Yh, __half* __restrict__ Yl,
    int C, int O, int mode, int b, int o0, int n0,
    __nv_bfloat16* sW, __nv_bfloat16* sX)
{
    const int tid = threadIdx.x;
    const int lane = tid & 31;
    const int w  = tid >> 5;
    const int lg = lane >> 2;
    const int lt = lane & 3;
    const int ow = (w & 3) * 16;
    const int nw = (w >> 2) * 32;

    const int lhalf = tid >> 7;
    const int li    = tid & 127;
    const int wrow  = li >> 1, wchk = (li & 1) * 8;
    const int xrow  = li >> 3, xchk = (li & 7) * 8;
    const __nv_bfloat16* Wsrc = lhalf ? Wl : Wh;
    const __nv_bfloat16* Xsrc = lhalf ? Xl : Xh;

    const int steps = C / 16;
    #define SW(buf, half) (sW + ((buf) * 2 + (half)) * 64 * PWSTR)
    #define SX(buf, half) (sX + ((buf) * 2 + (half)) * 16 * PXSTR)

    cp16(SW(0, lhalf) + wrow * PWSTR + wchk, Wsrc + (size_t)(o0 + wrow) * C + wchk);
    cp16(SX(0, lhalf) + xrow * PXSTR + xchk, Xsrc + (size_t)xrow * NN + n0 + xchk);
    cp_commit();

    float Oc[4][4];
    #pragma unroll
    for (int nt = 0; nt < 4; nt++)
        #pragma unroll
        for (int j = 0; j < 4; j++) Oc[nt][j] = 0.f;

    for (int s = 0; s < steps; s++) {
        const int cur = s & 1, nxt = cur ^ 1;
        if (s + 1 < steps) {
            int c0 = (s + 1) * 16;
            cp16(SW(nxt, lhalf) + wrow * PWSTR + wchk, Wsrc + (size_t)(o0 + wrow) * C + c0 + wchk);
            cp16(SX(nxt, lhalf) + xrow * PXSTR + xchk, Xsrc + (size_t)(c0 + xrow) * NN + n0 + xchk);
        }
        cp_commit();
        cp_wait<1>();
        __syncthreads();

        uint32_t ahf[4], alf[4];
        {
            int row = ow + (lane & 15);
            int col = (lane >> 4) * 8;
            ldm_x4(ahf, (uint32_t)__cvta_generic_to_shared(SW(cur, 0) + row * PWSTR + col));
            ldm_x4(alf, (uint32_t)__cvta_generic_to_shared(SW(cur, 1) + row * PWSTR + col));
        }
        #pragma unroll
        for (int nt = 0; nt < 4; nt++) {
            int nbase = nw + nt * 8;
            uint32_t bh0, bh1, bl0, bl1;
            ldm_x2t(bh0, bh1, (uint32_t)__cvta_generic_to_shared(SX(cur, 0) + (lane & 15) * PXSTR + nbase));
            ldm_x2t(bl0, bl1, (uint32_t)__cvta_generic_to_shared(SX(cur, 1) + (lane & 15) * PXSTR + nbase));
            mma_bf16(Oc[nt], ahf, bh0, bh1);
            mma_bf16(Oc[nt], alf, bh0, bh1);
            mma_bf16(Oc[nt], ahf, bl0, bl1);
        }
        __syncthreads();
    }
    #undef SW
    #undef SX

    const float rs = rsqrtf(1.f + EPSV);
    const int oa = o0 + ow + lg;
    const int ob = oa + 8;
    const float sa = gbn[oa] * rs, ba = bbn[oa];
    const float sb = gbn[ob] * rs, bb2 = bbn[ob];

    #pragma unroll
    for (int nt = 0; nt < 4; nt++) {
        int n = n0 + nw + nt * 8 + 2 * lt;
        float ya0 = Oc[nt][0] * sa + ba;
        float ya1 = Oc[nt][1] * sa + ba;
        float yb0 = Oc[nt][2] * sb + bb2;
        float yb1 = Oc[nt][3] * sb + bb2;
        size_t ia = ((size_t)b * O + oa) * NN + n;
        size_t ib = ((size_t)b * O + ob) * NN + n;
        if (mode == 0) {
            *(float2*)&Y0[ia] = make_float2(ya0, ya1);
            *(float2*)&Y0[ib] = make_float2(yb0, yb1);
        } else if (mode == 1) {
            __half2 ha, hb, la, lb;
            ha.x = __float2half_rn(ya0);
            ha.y = __float2half_rn(ya1);
            hb.x = __float2half_rn(yb0);
            hb.y = __float2half_rn(yb1);
            la.x = __float2half_rn(ya0 - __half2float(ha.x));
            la.y = __float2half_rn(ya1 - __half2float(ha.y));
            lb.x = __float2half_rn(yb0 - __half2float(hb.x));
            lb.y = __float2half_rn(yb1 - __half2float(hb.y));
            *(__half2*)&Yh[ia] = ha;
            *(__half2*)&Yh[ib] = hb;
            *(__half2*)&Yl[ia] = la;
            *(__half2*)&Yl[ib] = lb;
        } else {
            __half2 va2, vb2;
            va2.x = __float2half_rn(ya0);
            va2.y = __float2half_rn(ya1);
            vb2.x = __float2half_rn(yb0);
            vb2.y = __float2half_rn(yb1);
            *(__half2*)&Yh[ia] = va2;
            *(__half2*)&Yh[ib] = vb2;
        }
    }
}

// Fused Q/K/V projection: blockIdx.y segments (0-3 Q, 4-7 K, 8-23 V)
__global__ __launch_bounds__(256, 2)
void proj_qkv_kernel(const __nv_bfloat16* __restrict__ xh, const __nv_bfloat16* __restrict__ xl,
                     const __nv_bfloat16* __restrict__ wqh, const __nv_bfloat16* __restrict__ wql,
                     const float* __restrict__ gq,  const float* __restrict__ bq,
                     const __nv_bfloat16* __restrict__ wkh, const __nv_bfloat16* __restrict__ wkl,
                     const float* __restrict__ gk,  const float* __restrict__ bk,
                     const __nv_bfloat16* __restrict__ wvh, const __nv_bfloat16* __restrict__ wvl,
                     const float* __restrict__ gv,  const float* __restrict__ bv,
                     __half* __restrict__ qh, __half* __restrict__ ql,
                     __half* __restrict__ kh, __half* __restrict__ kl,
                     __half* __restrict__ v)
{
    __shared__ __align__(16) __nv_bfloat16 sW[2 * 2 * 64 * PWSTR];
    __shared__ __align__(16) __nv_bfloat16 sX[2 * 2 * 16 * PXSTR];

    const int seg = blockIdx.y;
    const int b   = blockIdx.z;
    const int n0  = blockIdx.x * 64;

    const __nv_bfloat16* Wh; const __nv_bfloat16* Wl; const float* g; const float* be;
    __half* Yh = nullptr; __half* Yl = nullptr;
    int O, mode, o0;
    if (seg < 4)      { Wh = wqh; Wl = wql; g = gq; be = bq; Yh = qh; Yl = ql; O = CCH;  mode = 1; o0 = seg * 64; }
    else if (seg < 8) { Wh = wkh; Wl = wkl; g = gk; be = bk; Yh = kh; Yl = kl; O = CCH;  mode = 1; o0 = (seg - 4) * 64; }
    else              { Wh = wvh; Wl = wvl; g = gv; be = bv; Yh = v;  O = DHCH; mode = 2; o0 = (seg - 8) * 64; }

    proj_body(xh + (size_t)b * CCH * NN, xl + (size_t)b * CCH * NN,
              Wh, Wl, g, be, nullptr, Yh, Yl, CCH, O, mode, b, o0, n0, sW, sX);
}

// Final projection (C=1024, input = xx bf16 pair from attn)
__global__ __launch_bounds__(256, 2)
void proj_out_kernel(const __nv_bfloat16* __restrict__ xxh, const __nv_bfloat16* __restrict__ xxl,
                     const __nv_bfloat16* __restrict__ wph, const __nv_bfloat16* __restrict__ wpl,
                     const float* __restrict__ gp,  const float* __restrict__ bp,
                     float* __restrict__ out)
{
    __shared__ __align__(16) __nv_bfloat16 sW[2 * 2 * 64 * PWSTR];
    __shared__ __align__(16) __nv_bfloat16 sX[2 * 2 * 16 * PXSTR];

    const int b  = blockIdx.z;
    const int o0 = blockIdx.y * 64;
    const int n0 = blockIdx.x * 64;

    proj_body(xxh + (size_t)b * DHCH * NN, xxl + (size_t)b * DHCH * NN,
              wph, wpl, gp, bp, out, nullptr, nullptr,
              DHCH, CCH, /*mode=*/0, b, o0, n0, sW, sX);
}

// ---------------------------------------------------------------------------
// Fused attention, all-fp16 tensor path.
//   S = QK^T: fp16 pairs, 3-term, m16n8k16 (12 HMMA/warp/tile).
//   P' = exp(S - 16) stored fp16; PV: fp16 m16n8k16 (16 HMMA/warp/tile).
// pool (bytes):
//   K bufs: buf i @ i*5120 (hi@0, lo@2560), rows 32 x 80B
//   V  @10240: 128 rows x 80B (fp16, 32 m + pad)
//   P  @20480: 64 rows x 80B (fp16)
//   sums @25600: 64 floats
//   Q staging: Qh @20480 (P region), Ql @5120 (K buf1)
// ---------------------------------------------------------------------------
#define KSTRH 40   // halves per K row (80B)
#define QSTRH 40
#define VSTRH 40
#define PSTRH 40
#define POOL_BYTES 25856

__global__ __launch_bounds__(256, 2)
void attn_mma_kernel(const __half* __restrict__ Qh, const __half* __restrict__ Ql,
                     const __half* __restrict__ Kh, const __half* __restrict__ Kl,
                     const __half* __restrict__ V,
                     __nv_bfloat16* __restrict__ XXh, __nv_bfloat16* __restrict__ XXl)
{
    __shared__ __align__(16) char pool[POOL_BYTES];
    __half* sV   = (__half*)(pool + 10240);
    __half* sP   = (__half*)(pool + 20480);
    float*  sSum = (float*)(pool + 25600);
    __half* stQh = (__half*)(pool + 20480);  // prologue only
    __half* stQl = (__half*)(pool + 5120);   // prologue only

    const int tid  = threadIdx.x;
    const int lane = tid & 31;
    const int w    = tid >> 5;
    const int lg   = lane >> 2;
    const int lt   = lane & 3;

    const int n0 = blockIdx.x * 64;
    const int h  = blockIdx.y;
    const int b  = blockIdx.z;

    const __half* QhB = Qh + ((size_t)b * CCH + h * KDIM) * NN;
    const __half* QlB = Ql + ((size_t)b * CCH + h * KDIM) * NN;
    const __half* KhB = Kh + ((size_t)b * CCH + h * KDIM) * NN;
    const __half* KlB = Kl + ((size_t)b * CCH + h * KDIM) * NN;
    const __half* VB  = V  + ((size_t)b * DHCH + h * DDIM) * NN;

    // cp.async maps. K: hi/lo (32kd x 32m fp16, 64B rows): 256 threads x 16B.
    const int khalf = tid >> 7;
    const int kr    = (tid & 127) >> 2;
    const int kcol  = (tid & 3) * 8;     // halves

    // ---- prologue: issue K0 (buf0) + V0
    {
        const __half* src = khalf ? KlB : KhB;
        cp16(pool + khalf * 2560 + kr * 80 + kcol * 2, src + (size_t)kr * NN + kcol);
    }
    #pragma unroll
    for (int j = 0; j < 2; j++) {
        int idx = tid + j * 256;
        int d = idx >> 2, ch = (idx & 3) * 8;
        cp16(sV + d * VSTRH + ch, VB + (size_t)d * NN + ch);
    }
    cp_commit();

    // ---- stage Q tiles transposed [q][kd] fp16
    #pragma unroll
    for (int i = 0; i < 4; i++) {
        int t = tid + i * 256;
        int kd = t >> 5, qp = t & 31;
        __half2 vh = *(const __half2*)&QhB[(size_t)kd * NN + n0 + 2 * qp];
        __half2 vl = *(const __half2*)&QlB[(size_t)kd * NN + n0 + 2 * qp];
        stQh[(2 * qp) * QSTRH + kd]     = vh.x;
        stQh[(2 * qp + 1) * QSTRH + kd] = vh.y;
        stQl[(2 * qp) * QSTRH + kd]     = vl.x;
        stQl[(2 * qp + 1) * QSTRH + kd] = vl.y;
    }
    if (tid < 64) sSum[tid] = 0.f;
    __syncthreads();

    // ---- hoist Q A-fragments via ldmatrix.x4
    const int qbase = (w & 3) * 16;
    const int qrS   = qbase + lg;
    uint32_t ah[2][4], al[2][4];
    #pragma unroll
    for (int kt = 0; kt < 2; kt++) {
        int row = qbase + (lane & 15);
        int col = kt * 16 + (lane >> 4) * 8;
        ldm_x4(ah[kt], (uint32_t)__cvta_generic_to_shared(&stQh[row * QSTRH + col]));
        ldm_x4(al[kt], (uint32_t)__cvta_generic_to_shared(&stQl[row * QSTRH + col]));
    }
    __syncthreads();   // staging regions (P, Kbuf1) now free

    float Oc[8][4];
    #pragma unroll
    for (int nt = 0; nt < 8; nt++)
        #pragma unroll
        for (int j = 0; j < 4; j++) Oc[nt][j] = 0.f;

    float rsum0 = 0.f, rsum1 = 0.f;
    const int n0w = (w >> 2) * 16;
    const int d0w = w * 16;

    const int NTILE = NN / 32;    // 72
    for (int i = 0; i < NTILE; i++) {
        cp_wait<0>();
        __syncthreads();                              // [sync1]

        char* curK = pool + (i & 1) * 5120;
        char* nxtK = pool + ((i + 1) & 1) * 5120;

        if (i + 1 < NTILE) {
            int m1 = (i + 1) * 32;
            const __half* src = khalf ? KlB : KhB;
            cp16(nxtK + khalf * 2560 + kr * 80 + kcol * 2, src + (size_t)kr * NN + m1 + kcol);
        }

        // ---- S = Q K^T (fp16 pair, 3-term); warp: 16q x 16m
        __half* cKh = (__half*)curK;
        __half* cKl = (__half*)(curK + 2560);
        float sc[2][4];
        sc[0][0] = sc[0][1] = sc[0][2] = sc[0][3] = 0.f;
        sc[1][0] = sc[1][1] = sc[1][2] = sc[1][3] = 0.f;
        #pragma unroll
        for (int kt = 0; kt < 2; kt++) {
            int krow = kt * 16 + (lane & 7) + ((lane >> 3) & 1) * 8;
            int kcolm = n0w + ((lane >> 4) & 1) * 8;
            uint32_t bh[4], bl[4];
            ldm_x4t(bh, (uint32_t)__cvta_generic_to_shared(&cKh[krow * KSTRH + kcolm]));
            ldm_x4t(bl, (uint32_t)__cvta_generic_to_shared(&cKl[krow * KSTRH + kcolm]));
            mma_f16(sc[0], ah[kt], bh[0], bh[1]);
            mma_f16(sc[0], al[kt], bh[0], bh[1]);
            mma_f16(sc[0], ah[kt], bl[0], bl[1]);
            mma_f16(sc[1], ah[kt], bh[2], bh[3]);
            mma_f16(sc[1], al[kt], bh[2], bh[3]);
            mma_f16(sc[1], ah[kt], bl[2], bl[3]);
        }

        // ---- hoist this warp's V_i fragments (16 d-rows) via ldmatrix.x4
        uint32_t va[2][4];
        #pragma unroll
        for (int kt = 0; kt < 2; kt++) {
            int row = d0w + (lane & 15);
            int col = kt * 16 + (lane >> 4) * 8;
            ldm_x4(va[kt], (uint32_t)__cvta_generic_to_shared(&sV[row * VSTRH + col]));
        }

        // ---- P' = exp(S - 16) as fp16; row sums from the rounded values
        #pragma unroll
        for (int nt = 0; nt < 2; nt++) {
            __half2 pa, pb2;
            pa.x  = __float2half_rn(fast_exp(sc[nt][0] - SSHIFT));
            pa.y  = __float2half_rn(fast_exp(sc[nt][1] - SSHIFT));
            pb2.x = __float2half_rn(fast_exp(sc[nt][2] - SSHIFT));
            pb2.y = __float2half_rn(fast_exp(sc[nt][3] - SSHIFT));
            rsum0 += __half2float(pa.x) + __half2float(pa.y);
            rsum1 += __half2float(pb2.x) + __half2float(pb2.y);
            int col = n0w + nt * 8 + 2 * lt;
            *(__half2*)&sP[qrS * PSTRH + col]       = pa;
            *(__half2*)&sP[(qrS + 8) * PSTRH + col] = pb2;
        }
        __syncthreads();                              // [sync2]

        // issue V(i+1) (V_i hoisted by all warps)
        if (i + 1 < NTILE) {
            int m1 = (i + 1) * 32;
            #pragma unroll
            for (int j = 0; j < 2; j++) {
                int idx = tid + j * 256;
                int d = idx >> 2, ch = (idx & 3) * 8;
                cp16(sV + d * VSTRH + ch, VB + (size_t)d * NN + m1 + ch);
            }
        }
        cp_commit();

        // ---- O += V * P'^T (fp16); warp: 16d x 64q
        #pragma unroll
        for (int kt = 0; kt < 2; kt++) {
            #pragma unroll
            for (int ntp = 0; ntp < 4; ntp++) {
                int q0 = ntp * 16;
                uint32_t pb[4];
                int prow = q0 + (lane & 7) + ((lane >> 4) & 1) * 8;
                int pcol = kt * 16 + ((lane >> 3) & 1) * 8;
                ldm_x4(pb, (uint32_t)__cvta_generic_to_shared(&sP[prow * PSTRH + pcol]));
                mma_f16(Oc[ntp * 2],     va[kt], pb[0], pb[1]);
                mma_f16(Oc[ntp * 2 + 1], va[kt], pb[2], pb[3]);
            }
        }
    }

    // ---- fold row sums
    rsum0 += __shfl_xor_sync(0xffffffffu, rsum0, 1);
    rsum0 += __shfl_xor_sync(0xffffffffu, rsum0, 2);
    rsum1 += __shfl_xor_sync(0xffffffffu, rsum1, 1);
    rsum1 += __shfl_xor_sync(0xffffffffu, rsum1, 2);
    if (lt == 0) {
        atomicAdd(&sSum[qrS], rsum0);
        atomicAdd(&sSum[qrS + 8], rsum1);
    }
    __syncthreads();
    if (tid < 64) sSum[tid] = 1.0f / sSum[tid];
    __syncthreads();

    // ---- store relu(o) as bf16 hi/lo pair, [d][q]
    __nv_bfloat16* XhB = XXh + ((size_t)b * DHCH + h * DDIM) * NN;
    __nv_bfloat16* XlB = XXl + ((size_t)b * DHCH + h * DDIM) * NN;
    #pragma unroll
    for (int nt = 0; nt < 8; nt++) {
        int qc = nt * 8 + 2 * lt;
        float i0 = sSum[qc], i1 = sSum[qc + 1];
        float o00 = fmaxf(Oc[nt][0] * i0, 0.f);
        float o01 = fmaxf(Oc[nt][1] * i1, 0.f);
        float o10 = fmaxf(Oc[nt][2] * i0, 0.f);
        float o11 = fmaxf(Oc[nt][3] * i1, 0.f);
        __nv_bfloat162 h0, l0, h1, l1;
        h0.x = __float2bfloat16_rn(o00);
        h0.y = __float2bfloat16_rn(o01);
        h1.x = __float2bfloat16_rn(o10);
        h1.y = __float2bfloat16_rn(o11);
        l0.x = __float2bfloat16_rn(o00 - __bfloat162float(h0.x));
        l0.y = __float2bfloat16_rn(o01 - __bfloat162float(h0.y));
        l1.x = __float2bfloat16_rn(o10 - __bfloat162float(h1.x));
        l1.y = __float2bfloat16_rn(o11 - __bfloat162float(h1.y));
        size_t ia = (size_t)(d0w + lg) * NN + n0 + qc;
        size_t ib = (size_t)(d0w + 8 + lg) * NN + n0 + qc;
        *(__nv_bfloat162*)&XhB[ia] = h0;
        *(__nv_bfloat162*)&XlB[ia] = l0;
        *(__nv_bfloat162*)&XhB[ib] = h1;
        *(__nv_bfloat162*)&XlB[ib] = l1;
    }
}

// ---------------------------------------------------------------------------
extern "C" void kernel_launch(void* const* d_in, const int* in_sizes, int n_in,
                              void* d_out, int out_size)
{
    const float* x  = (const float*)d_in[0];
    const float* wq = (const float*)d_in[1];
    const float* gq = (const float*)d_in[2];
    const float* bq = (const float*)d_in[3];
    const float* wk = (const float*)d_in[4];
    const float* gk = (const float*)d_in[5];
    const float* bk = (const float*)d_in[6];
    const float* wv = (const float*)d_in[7];
    const float* gv = (const float*)d_in[8];
    const float* bv = (const float*)d_in[9];
    const float* wp = (const float*)d_in[10];
    const float* gp = (const float*)d_in[11];
    const float* bp = (const float*)d_in[12];
    float* out = (float*)d_out;

    __nv_bfloat16 *xh, *xl, *xxh, *xxl;
    __nv_bfloat16 *wqh, *wql, *wkh, *wkl, *wvh, *wvl, *wph, *wpl;
    __half *qh, *ql, *kh, *kl, *v;
    cudaGetSymbolAddress((void**)&xh,  g_xh);
    cudaGetSymbolAddress((void**)&xl,  g_xl);
    cudaGetSymbolAddress((void**)&qh,  g_qh);
    cudaGetSymbolAddress((void**)&ql,  g_ql);
    cudaGetSymbolAddress((void**)&kh,  g_kh);
    cudaGetSymbolAddress((void**)&kl,  g_kl);
    cudaGetSymbolAddress((void**)&v,   g_v);
    cudaGetSymbolAddress((void**)&xxh, g_xxh);
    cudaGetSymbolAddress((void**)&xxl, g_xxl);
    cudaGetSymbolAddress((void**)&wqh, g_wqh);
    cudaGetSymbolAddress((void**)&wql, g_wql);
    cudaGetSymbolAddress((void**)&wkh, g_wkh);
    cudaGetSymbolAddress((void**)&wkl, g_wkl);
    cudaGetSymbolAddress((void**)&wvh, g_wvh);
    cudaGetSymbolAddress((void**)&wvl, g_wvl);
    cudaGetSymbolAddress((void**)&wph, g_wph);
    cudaGetSymbolAddress((void**)&wpl, g_wpl);

    // 1) split weights + x to bf16 pairs
    prep_split_kernel<<<dim3(256, 5), 256>>>(wq, wk, wv, wp, x,
                                             wqh, wql, wkh, wkl,
                                             wvh, wvl, wph, wpl, xh, xl);

    // 2) fused Q/K/V projections (bf16 3-MMA, fp16 outputs)
    proj_qkv_kernel<<<dim3(NN / 64, 24, BB), 256>>>(xh, xl,
        wqh, wql, gq, bq, wkh, wkl, gk, bk, wvh, wvl, gv, bv,
        qh, ql, kh, kl, v);

    // 3) fused attention (all-fp16 tensor path)
    attn_mma_kernel<<<dim3(NN / 64, NHEAD, BB), 256>>>(qh, ql, kh, kl, v, xxh, xxl);

    // 4) output projection + BN (bf16 3-MMA)
    proj_out_kernel<<<dim3(NN / 64, CCH / 64, BB), 256>>>(xxh, xxl, wph, wpl, gp, bp, out);
}

// round 11
// speedup vs baseline: 5.7314x; 1.1393x over previous
#include <cuda_runtime.h>
#include <cuda_bf16.h>
#include <cuda_fp16.h>
#include <math_constants.h>
#include <cstdint>

#define EPSV 1e-5f

// Problem constants
#define NN    2304
#define NHEAD 8
#define KDIM  32
#define DDIM  128
#define CCH   256
#define DHCH  1024
#define BB    4

#define SSHIFT 16.0f   // softmax shift: P' = exp(S - 16), keeps P' in fp16 range

// Scratch (allocation-free rule: device globals)
__device__ __nv_bfloat16 g_xh[BB * CCH * NN],  g_xl[BB * CCH * NN];     // x bf16 pair
__device__ __half        g_qh[BB * CCH * NN],  g_ql[BB * CCH * NN];     // Q fp16 pair
__device__ __half        g_kh[BB * CCH * NN],  g_kl[BB * CCH * NN];     // K fp16 pair
__device__ __half        g_v [BB * DHCH * NN];                          // V fp16
__device__ __half        g_xxf[BB * DHCH * NN];                         // relu(attn) fp16
__device__ __nv_bfloat16 g_wqh[CCH * CCH],  g_wql[CCH * CCH];
__device__ __nv_bfloat16 g_wkh[CCH * CCH],  g_wkl[CCH * CCH];
__device__ __nv_bfloat16 g_wvh[DHCH * CCH], g_wvl[DHCH * CCH];
__device__ __half        g_wpf[CCH * DHCH];                             // wp fp16

// ---------------------------------------------------------------------------
// helpers
// ---------------------------------------------------------------------------
__device__ __forceinline__ void mma_bf16(float c[4], const uint32_t a[4],
                                         uint32_t b0, uint32_t b1) {
    asm volatile(
        "mma.sync.aligned.m16n8k16.row.col.f32.bf16.bf16.f32 "
        "{%0,%1,%2,%3}, {%4,%5,%6,%7}, {%8,%9}, {%0,%1,%2,%3};\n"
        : "+f"(c[0]), "+f"(c[1]), "+f"(c[2]), "+f"(c[3])
        : "r"(a[0]), "r"(a[1]), "r"(a[2]), "r"(a[3]), "r"(b0), "r"(b1));
}
__device__ __forceinline__ void mma_f16(float c[4], const uint32_t a[4],
                                        uint32_t b0, uint32_t b1) {
    asm volatile(
        "mma.sync.aligned.m16n8k16.row.col.f32.f16.f16.f32 "
        "{%0,%1,%2,%3}, {%4,%5,%6,%7}, {%8,%9}, {%0,%1,%2,%3};\n"
        : "+f"(c[0]), "+f"(c[1]), "+f"(c[2]), "+f"(c[3])
        : "r"(a[0]), "r"(a[1]), "r"(a[2]), "r"(a[3]), "r"(b0), "r"(b1));
}

__device__ __forceinline__ void ldm_x4(uint32_t r[4], uint32_t addr) {
    asm volatile("ldmatrix.sync.aligned.m8n8.x4.shared.b16 {%0,%1,%2,%3}, [%4];"
        : "=r"(r[0]), "=r"(r[1]), "=r"(r[2]), "=r"(r[3]) : "r"(addr));
}
__device__ __forceinline__ void ldm_x4t(uint32_t r[4], uint32_t addr) {
    asm volatile("ldmatrix.sync.aligned.m8n8.x4.trans.shared.b16 {%0,%1,%2,%3}, [%4];"
        : "=r"(r[0]), "=r"(r[1]), "=r"(r[2]), "=r"(r[3]) : "r"(addr));
}
__device__ __forceinline__ void ldm_x2t(uint32_t& r0, uint32_t& r1, uint32_t addr) {
    asm volatile("ldmatrix.sync.aligned.m8n8.x2.trans.shared.b16 {%0,%1}, [%2];"
        : "=r"(r0), "=r"(r1) : "r"(addr));
}

__device__ __forceinline__ void cp16(void* sdst, const void* gsrc) {
    uint32_t s = (uint32_t)__cvta_generic_to_shared(sdst);
    asm volatile("cp.async.ca.shared.global [%0], [%1], 16;" :: "r"(s), "l"(gsrc));
}
__device__ __forceinline__ void cp_commit() {
    asm volatile("cp.async.commit_group;");
}
template <int N>
__device__ __forceinline__ void cp_wait() {
    asm volatile("cp.async.wait_group %0;" :: "n"(N));
}

// ---------------------------------------------------------------------------
// Prep: split weights + x into bf16 hi/lo pairs; wp to single fp16.
// ---------------------------------------------------------------------------
__global__ void prep_split_kernel(const float* __restrict__ wq, const float* __restrict__ wk,
                                  const float* __restrict__ wv, const float* __restrict__ wp,
                                  const float* __restrict__ x,
                                  __nv_bfloat16* __restrict__ wqh, __nv_bfloat16* __restrict__ wql,
                                  __nv_bfloat16* __restrict__ wkh, __nv_bfloat16* __restrict__ wkl,
                                  __nv_bfloat16* __restrict__ wvh, __nv_bfloat16* __restrict__ wvl,
                                  __half* __restrict__ wpf,
                                  __nv_bfloat16* __restrict__ xh,  __nv_bfloat16* __restrict__ xl)
{
    const int task = blockIdx.y;
    if (task == 3) {
        int n = CCH * DHCH;
        for (int i = blockIdx.x * blockDim.x + threadIdx.x; i < n; i += gridDim.x * blockDim.x)
            wpf[i] = __float2half_rn(wp[i]);
        return;
    }
    const float* src; __nv_bfloat16* h; __nv_bfloat16* l; int n;
    switch (task) {
        case 0:  src = wq; h = wqh; l = wql; n = CCH * CCH;    break;
        case 1:  src = wk; h = wkh; l = wkl; n = CCH * CCH;    break;
        case 2:  src = wv; h = wvh; l = wvl; n = DHCH * CCH;   break;
        default: src = x;  h = xh;  l = xl;  n = BB * CCH * NN; break;
    }
    for (int i = blockIdx.x * blockDim.x + threadIdx.x; i < n; i += gridDim.x * blockDim.x) {
        float v = src[i];
        __nv_bfloat16 hv = __float2bfloat16_rn(v);
        h[i] = hv;
        l[i] = __float2bfloat16_rn(v - __bfloat162float(hv));
    }
}

// ---------------------------------------------------------------------------
// bf16-pair 3-MMA projection + BN (Q/K/V).
// mode 1: fp16 pair store (Q/K). mode 2: fp16 store (V).
// ---------------------------------------------------------------------------
#define PWSTR 24
#define PXSTR 72
__device__ __forceinline__ void proj_body(
    const __nv_bfloat16* __restrict__ Xh, const __nv_bfloat16* __restrict__ Xl,
    const __nv_bfloat16* __restrict__ Wh, const __nv_bfloat16* __restrict__ Wl,
    const float* __restrict__ gbn, const float* __restrict__ bbn,
    __half* __restrict__ Yh, __half* __restrict__ Yl,
    int C, int O, int mode, int b, int o0, int n0,
    __nv_bfloat16* sW, __nv_bfloat16* sX)
{
    const int tid = threadIdx.x;
    const int lane = tid & 31;
    const int w  = tid >> 5;
    const int lg = lane >> 2;
    const int lt = lane & 3;
    const int ow = (w & 3) * 16;
    const int nw = (w >> 2) * 32;

    const int lhalf = tid >> 7;
    const int li    = tid & 127;
    const int wrow  = li >> 1, wchk = (li & 1) * 8;
    const int xrow  = li >> 3, xchk = (li & 7) * 8;
    const __nv_bfloat16* Wsrc = lhalf ? Wl : Wh;
    const __nv_bfloat16* Xsrc = lhalf ? Xl : Xh;

    const int steps = C / 16;
    #define SWB(buf, hf) (sW + ((buf) * 2 + (hf)) * 64 * PWSTR)
    #define SXB(buf, hf) (sX + ((buf) * 2 + (hf)) * 16 * PXSTR)

    cp16(SWB(0, lhalf) + wrow * PWSTR + wchk, Wsrc + (size_t)(o0 + wrow) * C + wchk);
    cp16(SXB(0, lhalf) + xrow * PXSTR + xchk, Xsrc + (size_t)xrow * NN + n0 + xchk);
    cp_commit();

    float Oc[4][4];
    #pragma unroll
    for (int nt = 0; nt < 4; nt++)
        #pragma unroll
        for (int j = 0; j < 4; j++) Oc[nt][j] = 0.f;

    for (int s = 0; s < steps; s++) {
        const int cur = s & 1, nxt = cur ^ 1;
        if (s + 1 < steps) {
            int c0 = (s + 1) * 16;
            cp16(SWB(nxt, lhalf) + wrow * PWSTR + wchk, Wsrc + (size_t)(o0 + wrow) * C + c0 + wchk);
            cp16(SXB(nxt, lhalf) + xrow * PXSTR + xchk, Xsrc + (size_t)(c0 + xrow) * NN + n0 + xchk);
        }
        cp_commit();
        cp_wait<1>();
        __syncthreads();

        uint32_t ahf[4], alf[4];
        {
            int row = ow + (lane & 15);
            int col = (lane >> 4) * 8;
            ldm_x4(ahf, (uint32_t)__cvta_generic_to_shared(SWB(cur, 0) + row * PWSTR + col));
            ldm_x4(alf, (uint32_t)__cvta_generic_to_shared(SWB(cur, 1) + row * PWSTR + col));
        }
        #pragma unroll
        for (int nt = 0; nt < 4; nt++) {
            int nbase = nw + nt * 8;
            uint32_t bh0, bh1, bl0, bl1;
            ldm_x2t(bh0, bh1, (uint32_t)__cvta_generic_to_shared(SXB(cur, 0) + (lane & 15) * PXSTR + nbase));
            ldm_x2t(bl0, bl1, (uint32_t)__cvta_generic_to_shared(SXB(cur, 1) + (lane & 15) * PXSTR + nbase));
            mma_bf16(Oc[nt], ahf, bh0, bh1);
            mma_bf16(Oc[nt], alf, bh0, bh1);
            mma_bf16(Oc[nt], ahf, bl0, bl1);
        }
        __syncthreads();
    }
    #undef SWB
    #undef SXB

    const float rs = rsqrtf(1.f + EPSV);
    const int oa = o0 + ow + lg;
    const int ob = oa + 8;
    const float sa = gbn[oa] * rs, ba = bbn[oa];
    const float sb = gbn[ob] * rs, bb2 = bbn[ob];

    #pragma unroll
    for (int nt = 0; nt < 4; nt++) {
        int n = n0 + nw + nt * 8 + 2 * lt;
        float ya0 = Oc[nt][0] * sa + ba;
        float ya1 = Oc[nt][1] * sa + ba;
        float yb0 = Oc[nt][2] * sb + bb2;
        float yb1 = Oc[nt][3] * sb + bb2;
        size_t ia = ((size_t)b * O + oa) * NN + n;
        size_t ib = ((size_t)b * O + ob) * NN + n;
        if (mode == 1) {
            __half2 ha, hb, la, lb;
            ha.x = __float2half_rn(ya0);
            ha.y = __float2half_rn(ya1);
            hb.x = __float2half_rn(yb0);
            hb.y = __float2half_rn(yb1);
            la.x = __float2half_rn(ya0 - __half2float(ha.x));
            la.y = __float2half_rn(ya1 - __half2float(ha.y));
            lb.x = __float2half_rn(yb0 - __half2float(hb.x));
            lb.y = __float2half_rn(yb1 - __half2float(hb.y));
            *(__half2*)&Yh[ia] = ha;
            *(__half2*)&Yh[ib] = hb;
            *(__half2*)&Yl[ia] = la;
            *(__half2*)&Yl[ib] = lb;
        } else {
            __half2 va2, vb2;
            va2.x = __float2half_rn(ya0);
            va2.y = __float2half_rn(ya1);
            vb2.x = __float2half_rn(yb0);
            vb2.y = __float2half_rn(yb1);
            *(__half2*)&Yh[ia] = va2;
            *(__half2*)&Yh[ib] = vb2;
        }
    }
}

// Fused Q/K/V projection: blockIdx.y segments (0-3 Q, 4-7 K, 8-23 V)
__global__ __launch_bounds__(256, 2)
void proj_qkv_kernel(const __nv_bfloat16* __restrict__ xh, const __nv_bfloat16* __restrict__ xl,
                     const __nv_bfloat16* __restrict__ wqh, const __nv_bfloat16* __restrict__ wql,
                     const float* __restrict__ gq,  const float* __restrict__ bq,
                     const __nv_bfloat16* __restrict__ wkh, const __nv_bfloat16* __restrict__ wkl,
                     const float* __restrict__ gk,  const float* __restrict__ bk,
                     const __nv_bfloat16* __restrict__ wvh, const __nv_bfloat16* __restrict__ wvl,
                     const float* __restrict__ gv,  const float* __restrict__ bv,
                     __half* __restrict__ qh, __half* __restrict__ ql,
                     __half* __restrict__ kh, __half* __restrict__ kl,
                     __half* __restrict__ v)
{
    __shared__ __align__(16) __nv_bfloat16 sW[2 * 2 * 64 * PWSTR];
    __shared__ __align__(16) __nv_bfloat16 sX[2 * 2 * 16 * PXSTR];

    const int seg = blockIdx.y;
    const int b   = blockIdx.z;
    const int n0  = blockIdx.x * 64;

    const __nv_bfloat16* Wh; const __nv_bfloat16* Wl; const float* g; const float* be;
    __half* Yh = nullptr; __half* Yl = nullptr;
    int O, mode, o0;
    if (seg < 4)      { Wh = wqh; Wl = wql; g = gq; be = bq; Yh = qh; Yl = ql; O = CCH;  mode = 1; o0 = seg * 64; }
    else if (seg < 8) { Wh = wkh; Wl = wkl; g = gk; be = bk; Yh = kh; Yl = kl; O = CCH;  mode = 1; o0 = (seg - 4) * 64; }
    else              { Wh = wvh; Wl = wvl; g = gv; be = bv; Yh = v;  O = DHCH; mode = 2; o0 = (seg - 8) * 64; }

    proj_body(xh + (size_t)b * CCH * NN, xl + (size_t)b * CCH * NN,
              Wh, Wl, g, be, Yh, Yl, CCH, O, mode, b, o0, n0, sW, sX);
}

// ---------------------------------------------------------------------------
// Final projection, single fp16 (C=1024): out = BN(wp_f16 . xx_f16)
// ---------------------------------------------------------------------------
__global__ __launch_bounds__(256, 2)
void proj_out_f16_kernel(const __half* __restrict__ xx, const __half* __restrict__ wp,
                         const float* __restrict__ gp, const float* __restrict__ bp,
                         float* __restrict__ out)
{
    __shared__ __align__(16) __half sW[2 * 64 * PWSTR];
    __shared__ __align__(16) __half sX[2 * 16 * PXSTR];

    const int b  = blockIdx.z;
    const int o0 = blockIdx.y * 64;
    const int n0 = blockIdx.x * 64;
    const int tid = threadIdx.x;
    const int lane = tid & 31;
    const int w  = tid >> 5;
    const int lg = lane >> 2;
    const int lt = lane & 3;
    const int ow = (w & 3) * 16;
    const int nw = (w >> 2) * 32;

    const __half* Xb = xx + (size_t)b * DHCH * NN;

    const int sel = tid >> 7;
    const int li  = tid & 127;
    const int wrow = li >> 1, wchk = (li & 1) * 8;
    const int xrow = li >> 3, xchk = (li & 7) * 8;

    if (sel == 0) cp16(&sW[0 * 64 * PWSTR + wrow * PWSTR + wchk], wp + (size_t)(o0 + wrow) * DHCH + wchk);
    else          cp16(&sX[0 * 16 * PXSTR + xrow * PXSTR + xchk], Xb + (size_t)xrow * NN + n0 + xchk);
    cp_commit();

    float Oc[4][4];
    #pragma unroll
    for (int nt = 0; nt < 4; nt++)
        #pragma unroll
        for (int j = 0; j < 4; j++) Oc[nt][j] = 0.f;

    const int steps = DHCH / 16;   // 64
    for (int s = 0; s < steps; s++) {
        const int cur = s & 1, nxt = cur ^ 1;
        if (s + 1 < steps) {
            int c0 = (s + 1) * 16;
            if (sel == 0) cp16(&sW[nxt * 64 * PWSTR + wrow * PWSTR + wchk], wp + (size_t)(o0 + wrow) * DHCH + c0 + wchk);
            else          cp16(&sX[nxt * 16 * PXSTR + xrow * PXSTR + xchk], Xb + (size_t)(c0 + xrow) * NN + n0 + xchk);
        }
        cp_commit();
        cp_wait<1>();
        __syncthreads();

        __half* cW = sW + cur * 64 * PWSTR;
        __half* cX = sX + cur * 16 * PXSTR;
        uint32_t awf[4];
        {
            int row = ow + (lane & 15);
            int col = (lane >> 4) * 8;
            ldm_x4(awf, (uint32_t)__cvta_generic_to_shared(cW + row * PWSTR + col));
        }
        #pragma unroll
        for (int nt = 0; nt < 4; nt++) {
            int nbase = nw + nt * 8;
            uint32_t b0, b1;
            ldm_x2t(b0, b1, (uint32_t)__cvta_generic_to_shared(cX + (lane & 15) * PXSTR + nbase));
            mma_f16(Oc[nt], awf, b0, b1);
        }
        __syncthreads();
    }

    const float rs = rsqrtf(1.f + EPSV);
    const int oa = o0 + ow + lg;
    const int ob = oa + 8;
    const float sa = gp[oa] * rs, ba = bp[oa];
    const float sb = gp[ob] * rs, bb2 = bp[ob];

    #pragma unroll
    for (int nt = 0; nt < 4; nt++) {
        int n = n0 + nw + nt * 8 + 2 * lt;
        size_t ia = ((size_t)b * CCH + oa) * NN + n;
        size_t ib = ((size_t)b * CCH + ob) * NN + n;
        *(float2*)&out[ia] = make_float2(Oc[nt][0] * sa + ba, Oc[nt][1] * sa + ba);
        *(float2*)&out[ib] = make_float2(Oc[nt][2] * sb + bb2, Oc[nt][3] * sb + bb2);
    }
}

// ---------------------------------------------------------------------------
// Fused attention, all-fp16 tensor path; exp via MUFU (__expf).
// ---------------------------------------------------------------------------
#define KSTRH 40
#define QSTRH 40
#define VSTRH 40
#define PSTRH 40
#define POOL_BYTES 25856

__global__ __launch_bounds__(256, 2)
void attn_mma_kernel(const __half* __restrict__ Qh, const __half* __restrict__ Ql,
                     const __half* __restrict__ Kh, const __half* __restrict__ Kl,
                     const __half* __restrict__ V,
                     __half* __restrict__ XX)
{
    __shared__ __align__(16) char pool[POOL_BYTES];
    __half* sV   = (__half*)(pool + 10240);
    __half* sP   = (__half*)(pool + 20480);
    float*  sSum = (float*)(pool + 25600);
    __half* stQh = (__half*)(pool + 20480);  // prologue only
    __half* stQl = (__half*)(pool + 5120);   // prologue only

    const int tid  = threadIdx.x;
    const int lane = tid & 31;
    const int w    = tid >> 5;
    const int lg   = lane >> 2;
    const int lt   = lane & 3;

    const int n0 = blockIdx.x * 64;
    const int h  = blockIdx.y;
    const int b  = blockIdx.z;

    const __half* QhB = Qh + ((size_t)b * CCH + h * KDIM) * NN;
    const __half* QlB = Ql + ((size_t)b * CCH + h * KDIM) * NN;
    const __half* KhB = Kh + ((size_t)b * CCH + h * KDIM) * NN;
    const __half* KlB = Kl + ((size_t)b * CCH + h * KDIM) * NN;
    const __half* VB  = V  + ((size_t)b * DHCH + h * DDIM) * NN;

    const int khalf = tid >> 7;
    const int kr    = (tid & 127) >> 2;
    const int kcol  = (tid & 3) * 8;

    // ---- prologue: issue K0 (buf0) + V0
    {
        const __half* src = khalf ? KlB : KhB;
        cp16(pool + khalf * 2560 + kr * 80 + kcol * 2, src + (size_t)kr * NN + kcol);
    }
    #pragma unroll
    for (int j = 0; j < 2; j++) {
        int idx = tid + j * 256;
        int d = idx >> 2, ch = (idx & 3) * 8;
        cp16(sV + d * VSTRH + ch, VB + (size_t)d * NN + ch);
    }
    cp_commit();

    // ---- stage Q tiles transposed [q][kd] fp16
    #pragma unroll
    for (int i = 0; i < 4; i++) {
        int t = tid + i * 256;
        int kd = t >> 5, qp = t & 31;
        __half2 vh = *(const __half2*)&QhB[(size_t)kd * NN + n0 + 2 * qp];
        __half2 vl = *(const __half2*)&QlB[(size_t)kd * NN + n0 + 2 * qp];
        stQh[(2 * qp) * QSTRH + kd]     = vh.x;
        stQh[(2 * qp + 1) * QSTRH + kd] = vh.y;
        stQl[(2 * qp) * QSTRH + kd]     = vl.x;
        stQl[(2 * qp + 1) * QSTRH + kd] = vl.y;
    }
    if (tid < 64) sSum[tid] = 0.f;
    __syncthreads();

    // ---- hoist Q A-fragments via ldmatrix.x4
    const int qbase = (w & 3) * 16;
    const int qrS   = qbase + lg;
    uint32_t ah[2][4], al[2][4];
    #pragma unroll
    for (int kt = 0; kt < 2; kt++) {
        int row = qbase + (lane & 15);
        int col = kt * 16 + (lane >> 4) * 8;
        ldm_x4(ah[kt], (uint32_t)__cvta_generic_to_shared(&stQh[row * QSTRH + col]));
        ldm_x4(al[kt], (uint32_t)__cvta_generic_to_shared(&stQl[row * QSTRH + col]));
    }
    __syncthreads();

    float Oc[8][4];
    #pragma unroll
    for (int nt = 0; nt < 8; nt++)
        #pragma unroll
        for (int j = 0; j < 4; j++) Oc[nt][j] = 0.f;

    float rsum0 = 0.f, rsum1 = 0.f;
    const int n0w = (w >> 2) * 16;
    const int d0w = w * 16;

    const int NTILE = NN / 32;
    for (int i = 0; i < NTILE; i++) {
        cp_wait<0>();
        __syncthreads();                              // [sync1]

        char* curK = pool + (i & 1) * 5120;
        char* nxtK = pool + ((i + 1) & 1) * 5120;

        if (i + 1 < NTILE) {
            int m1 = (i + 1) * 32;
            const __half* src = khalf ? KlB : KhB;
            cp16(nxtK + khalf * 2560 + kr * 80 + kcol * 2, src + (size_t)kr * NN + m1 + kcol);
        }

        // ---- S = Q K^T (fp16 pair, 3-term); warp: 16q x 16m
        __half* cKh = (__half*)curK;
        __half* cKl = (__half*)(curK + 2560);
        float sc[2][4];
        sc[0][0] = sc[0][1] = sc[0][2] = sc[0][3] = 0.f;
        sc[1][0] = sc[1][1] = sc[1][2] = sc[1][3] = 0.f;
        #pragma unroll
        for (int kt = 0; kt < 2; kt++) {
            int krow = kt * 16 + (lane & 7) + ((lane >> 3) & 1) * 8;
            int kcolm = n0w + ((lane >> 4) & 1) * 8;
            uint32_t bh[4], bl[4];
            ldm_x4t(bh, (uint32_t)__cvta_generic_to_shared(&cKh[krow * KSTRH + kcolm]));
            ldm_x4t(bl, (uint32_t)__cvta_generic_to_shared(&cKl[krow * KSTRH + kcolm]));
            mma_f16(sc[0], ah[kt], bh[0], bh[1]);
            mma_f16(sc[0], al[kt], bh[0], bh[1]);
            mma_f16(sc[0], ah[kt], bl[0], bl[1]);
            mma_f16(sc[1], ah[kt], bh[2], bh[3]);
            mma_f16(sc[1], al[kt], bh[2], bh[3]);
            mma_f16(sc[1], ah[kt], bl[2], bl[3]);
        }

        // ---- hoist this warp's V_i fragments (16 d-rows) via ldmatrix.x4
        uint32_t va[2][4];
        #pragma unroll
        for (int kt = 0; kt < 2; kt++) {
            int row = d0w + (lane & 15);
            int col = kt * 16 + (lane >> 4) * 8;
            ldm_x4(va[kt], (uint32_t)__cvta_generic_to_shared(&sV[row * VSTRH + col]));
        }

        // ---- P' = exp(S - 16) (MUFU) as fp16; row sums from the rounded values
        #pragma unroll
        for (int nt = 0; nt < 2; nt++) {
            __half2 pa, pb2;
            pa.x  = __float2half_rn(__expf(sc[nt][0] - SSHIFT));
            pa.y  = __float2half_rn(__expf(sc[nt][1] - SSHIFT));
            pb2.x = __float2half_rn(__expf(sc[nt][2] - SSHIFT));
            pb2.y = __float2half_rn(__expf(sc[nt][3] - SSHIFT));
            rsum0 += __half2float(pa.x) + __half2float(pa.y);
            rsum1 += __half2float(pb2.x) + __half2float(pb2.y);
            int col = n0w + nt * 8 + 2 * lt;
            *(__half2*)&sP[qrS * PSTRH + col]       = pa;
            *(__half2*)&sP[(qrS + 8) * PSTRH + col] = pb2;
        }
        __syncthreads();                              // [sync2]

        // issue V(i+1) (V_i hoisted by all warps)
        if (i + 1 < NTILE) {
            int m1 = (i + 1) * 32;
            #pragma unroll
            for (int j = 0; j < 2; j++) {
                int idx = tid + j * 256;
                int d = idx >> 2, ch = (idx & 3) * 8;
                cp16(sV + d * VSTRH + ch, VB + (size_t)d * NN + m1 + ch);
            }
        }
        cp_commit();

        // ---- O += V * P'^T (fp16); warp: 16d x 64q
        #pragma unroll
        for (int kt = 0; kt < 2; kt++) {
            #pragma unroll
            for (int ntp = 0; ntp < 4; ntp++) {
                int q0 = ntp * 16;
                uint32_t pb[4];
                int prow = q0 + (lane & 7) + ((lane >> 4) & 1) * 8;
                int pcol = kt * 16 + ((lane >> 3) & 1) * 8;
                ldm_x4(pb, (uint32_t)__cvta_generic_to_shared(&sP[prow * PSTRH + pcol]));
                mma_f16(Oc[ntp * 2],     va[kt], pb[0], pb[1]);
                mma_f16(Oc[ntp * 2 + 1], va[kt], pb[2], pb[3]);
            }
        }
    }

    // ---- fold row sums
    rsum0 += __shfl_xor_sync(0xffffffffu, rsum0, 1);
    rsum0 += __shfl_xor_sync(0xffffffffu, rsum0, 2);
    rsum1 += __shfl_xor_sync(0xffffffffu, rsum1, 1);
    rsum1 += __shfl_xor_sync(0xffffffffu, rsum1, 2);
    if (lt == 0) {
        atomicAdd(&sSum[qrS], rsum0);
        atomicAdd(&sSum[qrS + 8], rsum1);
    }
    __syncthreads();
    if (tid < 64) sSum[tid] = 1.0f / sSum[tid];
    __syncthreads();

    // ---- store relu(o) as single fp16, [d][q]
    __half* XB = XX + ((size_t)b * DHCH + h * DDIM) * NN;
    #pragma unroll
    for (int nt = 0; nt < 8; nt++) {
        int qc = nt * 8 + 2 * lt;
        float i0 = sSum[qc], i1 = sSum[qc + 1];
        __half2 o0, o1;
        o0.x = __float2half_rn(fmaxf(Oc[nt][0] * i0, 0.f));
        o0.y = __float2half_rn(fmaxf(Oc[nt][1] * i1, 0.f));
        o1.x = __float2half_rn(fmaxf(Oc[nt][2] * i0, 0.f));
        o1.y = __float2half_rn(fmaxf(Oc[nt][3] * i1, 0.f));
        *(__half2*)&XB[(size_t)(d0w + lg) * NN + n0 + qc]     = o0;
        *(__half2*)&XB[(size_t)(d0w + 8 + lg) * NN + n0 + qc] = o1;
    }
}

// ---------------------------------------------------------------------------
extern "C" void kernel_launch(void* const* d_in, const int* in_sizes, int n_in,
                              void* d_out, int out_size)
{
    const float* x  = (const float*)d_in[0];
    const float* wq = (const float*)d_in[1];
    const float* gq = (const float*)d_in[2];
    const float* bq = (const float*)d_in[3];
    const float* wk = (const float*)d_in[4];
    const float* gk = (const float*)d_in[5];
    const float* bk = (const float*)d_in[6];
    const float* wv = (const float*)d_in[7];
    const float* gv = (const float*)d_in[8];
    const float* bv = (const float*)d_in[9];
    const float* wp = (const float*)d_in[10];
    const float* gp = (const float*)d_in[11];
    const float* bp = (const float*)d_in[12];
    float* out = (float*)d_out;

    __nv_bfloat16 *xh, *xl;
    __nv_bfloat16 *wqh, *wql, *wkh, *wkl, *wvh, *wvl;
    __half *qh, *ql, *kh, *kl, *v, *xxf, *wpf;
    cudaGetSymbolAddress((void**)&xh,  g_xh);
    cudaGetSymbolAddress((void**)&xl,  g_xl);
    cudaGetSymbolAddress((void**)&qh,  g_qh);
    cudaGetSymbolAddress((void**)&ql,  g_ql);
    cudaGetSymbolAddress((void**)&kh,  g_kh);
    cudaGetSymbolAddress((void**)&kl,  g_kl);
    cudaGetSymbolAddress((void**)&v,   g_v);
    cudaGetSymbolAddress((void**)&xxf, g_xxf);
    cudaGetSymbolAddress((void**)&wpf, g_wpf);
    cudaGetSymbolAddress((void**)&wqh, g_wqh);
    cudaGetSymbolAddress((void**)&wql, g_wql);
    cudaGetSymbolAddress((void**)&wkh, g_wkh);
    cudaGetSymbolAddress((void**)&wkl, g_wkl);
    cudaGetSymbolAddress((void**)&wvh, g_wvh);
    cudaGetSymbolAddress((void**)&wvl, g_wvl);

    // 1) split weights + x
    prep_split_kernel<<<dim3(256, 5), 256>>>(wq, wk, wv, wp, x,
                                             wqh, wql, wkh, wkl,
                                             wvh, wvl, wpf, xh, xl);

    // 2) fused Q/K/V projections (bf16 3-MMA, fp16 outputs)
    proj_qkv_kernel<<<dim3(NN / 64, 24, BB), 256>>>(xh, xl,
        wqh, wql, gq, bq, wkh, wkl, gk, bk, wvh, wvl, gv, bv,
        qh, ql, kh, kl, v);

    // 3) fused attention (fp16 tensor path, MUFU exp)
    attn_mma_kernel<<<dim3(NN / 64, NHEAD, BB), 256>>>(qh, ql, kh, kl, v, xxf);

    // 4) output projection + BN (single fp16, 1-MMA)
    proj_out_f16_kernel<<<dim3(NN / 64, CCH / 64, BB), 256>>>(xxf, wpf, gp, bp, out);
}